// round 2
// baseline (speedup 1.0000x reference)
#include <cuda_runtime.h>
#include <cuda_fp16.h>
#include <cstdint>

typedef unsigned long long ull;

// ---------------- scratch (static device allocations; no cudaMalloc) ----------------
__device__ float  g_xw1[268435456];  // [T=512][B=1024][n=512] fp32, n = j*4+q
__device__ float  g_xw2[134217728];  // [T=512][B=1024][n=256] fp32, n = j*4+q
__device__ __half g_hs1[67108864];   // [T=512][B=1024][128]   fp16

// ---------------- helpers ----------------
__device__ __forceinline__ ull pack2(float lo, float hi){
    ull r; asm("mov.b64 %0, {%1, %2};" : "=l"(r) : "f"(lo), "f"(hi)); return r;
}
__device__ __forceinline__ float2 unpack2(ull v){
    float2 f; asm("mov.b64 {%0, %1}, %2;" : "=f"(f.x), "=f"(f.y) : "l"(v)); return f;
}
__device__ __forceinline__ ull ffma2(ull a, ull b, ull c){
    ull d; asm("fma.rn.f32x2 %0, %1, %2, %3;" : "=l"(d) : "l"(a), "l"(b), "l"(c)); return d;
}
__device__ __forceinline__ float sigf(float x){ return 1.f / (1.f + __expf(-x)); }
__device__ __forceinline__ float tanh_f(float x){ return 1.f - 2.f / (__expf(2.f * x) + 1.f); }

__device__ __forceinline__ void mma16816(float& c0, float& c1, float& c2, float& c3,
                                         uint32_t a0, uint32_t a1, uint32_t a2, uint32_t a3,
                                         uint32_t b0, uint32_t b1){
    asm("mma.sync.aligned.m16n8k16.row.col.f32.f16.f16.f32 "
        "{%0,%1,%2,%3}, {%4,%5,%6,%7}, {%8,%9}, {%0,%1,%2,%3};"
        : "+f"(c0), "+f"(c1), "+f"(c2), "+f"(c3)
        : "r"(a0), "r"(a1), "r"(a2), "r"(a3), "r"(b0), "r"(b1));
}

__device__ __forceinline__ uint32_t f2h2(float lo, float hi){
    __half2 h = __floats2half2_rn(lo, hi);
    return *(uint32_t*)&h;
}

// =====================================================================
// GEMM1 (unchanged): xw1[(t,b), n] = X @ W1_ih^T + bias, n = j*4+q, g = q*128+j
// =====================================================================
__global__ void __launch_bounds__(256) gemm1_kernel(
    const float* __restrict__ X, const float* __restrict__ W,
    const float* __restrict__ bih, const float* __restrict__ bhh)
{
    extern __shared__ float sm[];
    float* sAT = sm;               // [100][132]
    float* sB  = sm + 100 * 132;   // [100][68]
    const int tid = threadIdx.x;
    const int cb = blockIdx.x, rb = blockIdx.y;
    const size_t r0 = (size_t)rb * 128;

    const float* Ab = X + r0 * 100;
    for (int idx = tid; idx < 12800; idx += 256){
        int i = idx / 100, e = idx - i * 100;
        sAT[e * 132 + i] = Ab[idx];
    }
    for (int idx = tid; idx < 6400; idx += 256){
        int gi = idx / 100, k = idx - gi * 100;
        int q = gi >> 4, jo = gi & 15;
        int g = q * 128 + cb * 16 + jo;
        int n = jo * 4 + q;
        sB[k * 68 + n] = W[g * 100 + k];
    }
    __syncthreads();

    const int ty = tid >> 4, tx = tid & 15;
    ull acc[8][2];
    #pragma unroll
    for (int r = 0; r < 8; r++){ acc[r][0] = 0ull; acc[r][1] = 0ull; }

    const float* ap0 = sAT + ty * 8;
    const float* bp0 = sB  + tx * 4;
    #pragma unroll 2
    for (int k = 0; k < 100; k++){
        float4 a0 = *(const float4*)(ap0 + k * 132);
        float4 a1 = *(const float4*)(ap0 + k * 132 + 4);
        ulonglong2 bv = *(const ulonglong2*)(bp0 + k * 68);
        ull ap;
        ap = pack2(a0.x, a0.x); acc[0][0]=ffma2(ap,bv.x,acc[0][0]); acc[0][1]=ffma2(ap,bv.y,acc[0][1]);
        ap = pack2(a0.y, a0.y); acc[1][0]=ffma2(ap,bv.x,acc[1][0]); acc[1][1]=ffma2(ap,bv.y,acc[1][1]);
        ap = pack2(a0.z, a0.z); acc[2][0]=ffma2(ap,bv.x,acc[2][0]); acc[2][1]=ffma2(ap,bv.y,acc[2][1]);
        ap = pack2(a0.w, a0.w); acc[3][0]=ffma2(ap,bv.x,acc[3][0]); acc[3][1]=ffma2(ap,bv.y,acc[3][1]);
        ap = pack2(a1.x, a1.x); acc[4][0]=ffma2(ap,bv.x,acc[4][0]); acc[4][1]=ffma2(ap,bv.y,acc[4][1]);
        ap = pack2(a1.y, a1.y); acc[5][0]=ffma2(ap,bv.x,acc[5][0]); acc[5][1]=ffma2(ap,bv.y,acc[5][1]);
        ap = pack2(a1.z, a1.z); acc[6][0]=ffma2(ap,bv.x,acc[6][0]); acc[6][1]=ffma2(ap,bv.y,acc[6][1]);
        ap = pack2(a1.w, a1.w); acc[7][0]=ffma2(ap,bv.x,acc[7][0]); acc[7][1]=ffma2(ap,bv.y,acc[7][1]);
    }

    const int cbase = cb * 64 + tx * 4;
    float bias[4];
    #pragma unroll
    for (int c = 0; c < 4; c++){
        int cc = cbase + c; int j = cc >> 2, q = cc & 3; int g = q * 128 + j;
        bias[c] = bih[g] + bhh[g];
    }
    #pragma unroll
    for (int r = 0; r < 8; r++){
        size_t row = r0 + ty * 8 + r;          // row = b*512 + t
        int bidx = (int)(row >> 9);
        int tidx = (int)(row & 511);
        size_t o = ((size_t)tidx * 1024 + bidx) * 512 + cbase;
        float2 p0 = unpack2(acc[r][0]); float2 p1 = unpack2(acc[r][1]);
        float4 v = make_float4(p0.x + bias[0], p0.y + bias[1], p1.x + bias[2], p1.y + bias[3]);
        *(float4*)(g_xw1 + o) = v;
    }
}

// =====================================================================
// GEMM2 (unchanged): xw2 = hs1 @ W2_ih^T + bias, n = j*4+q, g = q*64+j
// =====================================================================
__global__ void __launch_bounds__(256) gemm2_kernel(
    const float* __restrict__ W, const float* __restrict__ bih, const float* __restrict__ bhh)
{
    extern __shared__ float sm[];
    float* sAT = sm;               // [128][132]
    float* sB  = sm + 128 * 132;   // [128][68]
    const int tid = threadIdx.x;
    const int cb = blockIdx.x, rb = blockIdx.y;
    const size_t rr0 = (size_t)rb * 128;

    const __half2* Ah2 = (const __half2*)(g_hs1 + rr0 * 128);
    for (int idx = tid; idx < 8192; idx += 256){
        int i = idx >> 6, k2 = idx & 63;
        float2 f = __half22float2(Ah2[i * 64 + k2]);
        sAT[(2 * k2)     * 132 + i] = f.x;
        sAT[(2 * k2 + 1) * 132 + i] = f.y;
    }
    for (int idx = tid; idx < 8192; idx += 256){
        int gi = idx >> 7, k = idx & 127;
        int q = gi >> 4, jo = gi & 15;
        int g = q * 64 + cb * 16 + jo;
        int n = jo * 4 + q;
        sB[k * 68 + n] = W[g * 128 + k];
    }
    __syncthreads();

    const int ty = tid >> 4, tx = tid & 15;
    ull acc[8][2];
    #pragma unroll
    for (int r = 0; r < 8; r++){ acc[r][0] = 0ull; acc[r][1] = 0ull; }

    const float* ap0 = sAT + ty * 8;
    const float* bp0 = sB  + tx * 4;
    #pragma unroll 2
    for (int k = 0; k < 128; k++){
        float4 a0 = *(const float4*)(ap0 + k * 132);
        float4 a1 = *(const float4*)(ap0 + k * 132 + 4);
        ulonglong2 bv = *(const ulonglong2*)(bp0 + k * 68);
        ull ap;
        ap = pack2(a0.x, a0.x); acc[0][0]=ffma2(ap,bv.x,acc[0][0]); acc[0][1]=ffma2(ap,bv.y,acc[0][1]);
        ap = pack2(a0.y, a0.y); acc[1][0]=ffma2(ap,bv.x,acc[1][0]); acc[1][1]=ffma2(ap,bv.y,acc[1][1]);
        ap = pack2(a0.z, a0.z); acc[2][0]=ffma2(ap,bv.x,acc[2][0]); acc[2][1]=ffma2(ap,bv.y,acc[2][1]);
        ap = pack2(a0.w, a0.w); acc[3][0]=ffma2(ap,bv.x,acc[3][0]); acc[3][1]=ffma2(ap,bv.y,acc[3][1]);
        ap = pack2(a1.x, a1.x); acc[4][0]=ffma2(ap,bv.x,acc[4][0]); acc[4][1]=ffma2(ap,bv.y,acc[4][1]);
        ap = pack2(a1.y, a1.y); acc[5][0]=ffma2(ap,bv.x,acc[5][0]); acc[5][1]=ffma2(ap,bv.y,acc[5][1]);
        ap = pack2(a1.z, a1.z); acc[6][0]=ffma2(ap,bv.x,acc[6][0]); acc[6][1]=ffma2(ap,bv.y,acc[6][1]);
        ap = pack2(a1.w, a1.w); acc[7][0]=ffma2(ap,bv.x,acc[7][0]); acc[7][1]=ffma2(ap,bv.y,acc[7][1]);
    }

    const int cbase = cb * 64 + tx * 4;
    float bias[4];
    #pragma unroll
    for (int c = 0; c < 4; c++){
        int cc = cbase + c; int j = cc >> 2, q = cc & 3; int g = q * 64 + j;
        bias[c] = bih[g] + bhh[g];
    }
    #pragma unroll
    for (int r = 0; r < 8; r++){
        size_t rr = rr0 + ty * 8 + r;
        size_t o = rr * 256 + cbase;
        float2 p0 = unpack2(acc[r][0]); float2 p1 = unpack2(acc[r][1]);
        float4 v = make_float4(p0.x + bias[0], p0.y + bias[1], p1.x + bias[2], p1.y + bias[3]);
        *(float4*)(g_xw2 + o) = v;
    }
}

// =====================================================================
// REC1 (tensor-core): 64 CTAs x 16 batch rows, 8 warps, W frags in regs.
// Per step: D[16,512] = h[16,128] @ W1_hh^T(col n=j*4+q) ; LSTM cell; h->SMEM+g_hs1.
// =====================================================================
__global__ void __launch_bounds__(256, 1) rec1_kernel(const float* __restrict__ Whh)
{
    __shared__ __half sH[2][16 * 136];   // double-buffered h, stride 136
    const int tid  = threadIdx.x;
    const int w    = tid >> 5;
    const int lane = tid & 31;
    const int gp   = lane >> 2;          // groupID: rows gp, gp+8 / B col offset
    const int tig  = lane & 3;
    const int b0   = blockIdx.x * 16;
    const bool odd = (lane & 1);

    // ---- load B fragments (W1_hh) once: 8 ntiles x 8 ktiles x 2 regs ----
    uint32_t bf[8][8][2];
    #pragma unroll
    for (int nt = 0; nt < 8; nt++){
        int n = w * 64 + nt * 8 + gp;    // column n = j*4+q
        int j = n >> 2, q = n & 3;
        const float* wr = Whh + (q * 128 + j) * 128;   // row g = q*128+j, K=128
        #pragma unroll
        for (int kt = 0; kt < 8; kt++){
            int k = kt * 16 + 2 * tig;
            float2 w0 = *(const float2*)(wr + k);
            float2 w1 = *(const float2*)(wr + k + 8);
            bf[nt][kt][0] = f2h2(w0.x, w0.y);
            bf[nt][kt][1] = f2h2(w1.x, w1.y);
        }
    }

    // zero read buffer 1 (h_{-1} = 0)
    for (int i = tid; i < 16 * 136; i += 256) sH[1][i] = __float2half(0.f);
    __syncthreads();

    float cst[8][2];
    #pragma unroll
    for (int nt = 0; nt < 8; nt++){ cst[nt][0] = 0.f; cst[nt][1] = 0.f; }

    const int r0 = gp, r1 = gp + 8;
    const int cA = w * 64 /*+ nt*8*/ + 2 * tig;   // per-ntile add nt*8

    for (int t = 0; t < 512; t++){
        const __half* hr = sH[1 - (t & 1)];
        __half*       hw = sH[t & 1];

        float acc[8][4];
        #pragma unroll
        for (int nt = 0; nt < 8; nt++){
            acc[nt][0] = 0.f; acc[nt][1] = 0.f; acc[nt][2] = 0.f; acc[nt][3] = 0.f;
        }

        #pragma unroll
        for (int kt = 0; kt < 8; kt++){
            int k0 = kt * 16 + 2 * tig;
            uint32_t a0 = *(const uint32_t*)(hr + r0 * 136 + k0);
            uint32_t a1 = *(const uint32_t*)(hr + r1 * 136 + k0);
            uint32_t a2 = *(const uint32_t*)(hr + r0 * 136 + k0 + 8);
            uint32_t a3 = *(const uint32_t*)(hr + r1 * 136 + k0 + 8);
            #pragma unroll
            for (int nt = 0; nt < 8; nt++)
                mma16816(acc[nt][0], acc[nt][1], acc[nt][2], acc[nt][3],
                         a0, a1, a2, a3, bf[nt][kt][0], bf[nt][kt][1]);
        }

        const size_t xb = ((size_t)t * 1024 + b0) * 512;
        #pragma unroll
        for (int nt = 0; nt < 8; nt++){
            int c = cA + nt * 8;
            float2 x0 = *(const float2*)(g_xw1 + xb + (size_t)r0 * 512 + c);
            float2 x1 = *(const float2*)(g_xw1 + xb + (size_t)r1 * 512 + c);
            float p0 = acc[nt][0] + x0.x;
            float p1 = acc[nt][1] + x0.y;
            float p2 = acc[nt][2] + x1.x;
            float p3 = acc[nt][3] + x1.y;
            float q0 = __shfl_xor_sync(0xffffffffu, p0, 1);
            float q1 = __shfl_xor_sync(0xffffffffu, p1, 1);
            float q2 = __shfl_xor_sync(0xffffffffu, p2, 1);
            float q3 = __shfl_xor_sync(0xffffffffu, p3, 1);
            float i0 = odd ? q0 : p0, i1 = odd ? q2 : p2;
            float f0 = odd ? q1 : p1, f1 = odd ? q3 : p3;
            float g0 = odd ? p0 : q0, g1 = odd ? p2 : q2;
            float o0 = odd ? p1 : q1, o1 = odd ? p3 : q3;
            float c0 = sigf(f0) * cst[nt][0] + sigf(i0) * tanh_f(g0);
            float c1 = sigf(f1) * cst[nt][1] + sigf(i1) * tanh_f(g1);
            cst[nt][0] = c0; cst[nt][1] = c1;
            float h0 = sigf(o0) * tanh_f(c0);
            float h1 = sigf(o1) * tanh_f(c1);
            if (!odd){
                int u = w * 16 + nt * 2 + (tig >> 1);
                hw[r0 * 136 + u] = __float2half(h0);
                hw[r1 * 136 + u] = __float2half(h1);
            }
        }
        __syncthreads();

        // coalesced copy h_t (16x128) -> g_hs1
        {
            int row  = tid >> 4;
            int col8 = (tid & 15) * 8;
            int4 v = *(const int4*)(hw + row * 136 + col8);
            *(int4*)(g_hs1 + ((size_t)t * 1024 + b0 + row) * 128 + col8) = v;
        }
    }
}

// =====================================================================
// REC2 (tensor-core) + fused FC head. 64 CTAs x 16 rows, 8 warps.
// Per step: D[16,256] = h[16,64] @ W2_hh^T(col n=j*4+q).
// =====================================================================
__global__ void __launch_bounds__(256, 1) rec2_kernel(
    const float* __restrict__ Whh,
    const float* __restrict__ fc1w, const float* __restrict__ fc1b,
    const float* __restrict__ fc2w, const float* __restrict__ fc2b,
    float* __restrict__ out)
{
    __shared__ __half sH[2][16 * 72];    // stride 72
    const int tid  = threadIdx.x;
    const int w    = tid >> 5;
    const int lane = tid & 31;
    const int gp   = lane >> 2;
    const int tig  = lane & 3;
    const int b0   = blockIdx.x * 16;
    const bool odd = (lane & 1);

    // B fragments: 4 ntiles x 4 ktiles x 2 regs
    uint32_t bf[4][4][2];
    #pragma unroll
    for (int nt = 0; nt < 4; nt++){
        int n = w * 32 + nt * 8 + gp;
        int j = n >> 2, q = n & 3;
        const float* wr = Whh + (q * 64 + j) * 64;   // row g = q*64+j, K=64
        #pragma unroll
        for (int kt = 0; kt < 4; kt++){
            int k = kt * 16 + 2 * tig;
            float2 w0 = *(const float2*)(wr + k);
            float2 w1 = *(const float2*)(wr + k + 8);
            bf[nt][kt][0] = f2h2(w0.x, w0.y);
            bf[nt][kt][1] = f2h2(w1.x, w1.y);
        }
    }

    for (int i = tid; i < 16 * 72; i += 256) sH[1][i] = __float2half(0.f);
    __syncthreads();

    float cst[4][2];
    #pragma unroll
    for (int nt = 0; nt < 4; nt++){ cst[nt][0] = 0.f; cst[nt][1] = 0.f; }

    const int r0 = gp, r1 = gp + 8;
    const int cA = w * 32 + 2 * tig;

    for (int t = 0; t < 512; t++){
        const __half* hr = sH[1 - (t & 1)];
        __half*       hw = sH[t & 1];

        float acc[4][4];
        #pragma unroll
        for (int nt = 0; nt < 4; nt++){
            acc[nt][0] = 0.f; acc[nt][1] = 0.f; acc[nt][2] = 0.f; acc[nt][3] = 0.f;
        }

        #pragma unroll
        for (int kt = 0; kt < 4; kt++){
            int k0 = kt * 16 + 2 * tig;
            uint32_t a0 = *(const uint32_t*)(hr + r0 * 72 + k0);
            uint32_t a1 = *(const uint32_t*)(hr + r1 * 72 + k0);
            uint32_t a2 = *(const uint32_t*)(hr + r0 * 72 + k0 + 8);
            uint32_t a3 = *(const uint32_t*)(hr + r1 * 72 + k0 + 8);
            #pragma unroll
            for (int nt = 0; nt < 4; nt++)
                mma16816(acc[nt][0], acc[nt][1], acc[nt][2], acc[nt][3],
                         a0, a1, a2, a3, bf[nt][kt][0], bf[nt][kt][1]);
        }

        const size_t xb = ((size_t)t * 1024 + b0) * 256;
        #pragma unroll
        for (int nt = 0; nt < 4; nt++){
            int c = cA + nt * 8;
            float2 x0 = *(const float2*)(g_xw2 + xb + (size_t)r0 * 256 + c);
            float2 x1 = *(const float2*)(g_xw2 + xb + (size_t)r1 * 256 + c);
            float p0 = acc[nt][0] + x0.x;
            float p1 = acc[nt][1] + x0.y;
            float p2 = acc[nt][2] + x1.x;
            float p3 = acc[nt][3] + x1.y;
            float q0 = __shfl_xor_sync(0xffffffffu, p0, 1);
            float q1 = __shfl_xor_sync(0xffffffffu, p1, 1);
            float q2 = __shfl_xor_sync(0xffffffffu, p2, 1);
            float q3 = __shfl_xor_sync(0xffffffffu, p3, 1);
            float i0 = odd ? q0 : p0, i1 = odd ? q2 : p2;
            float f0 = odd ? q1 : p1, f1 = odd ? q3 : p3;
            float g0 = odd ? p0 : q0, g1 = odd ? p2 : q2;
            float o0 = odd ? p1 : q1, o1 = odd ? p3 : q3;
            float c0 = sigf(f0) * cst[nt][0] + sigf(i0) * tanh_f(g0);
            float c1 = sigf(f1) * cst[nt][1] + sigf(i1) * tanh_f(g1);
            cst[nt][0] = c0; cst[nt][1] = c1;
            float h0 = sigf(o0) * tanh_f(c0);
            float h1 = sigf(o1) * tanh_f(c1);
            if (!odd){
                int u = w * 8 + nt * 2 + (tig >> 1);
                hw[r0 * 72 + u] = __float2half(h0);
                hw[r1 * 72 + u] = __float2half(h1);
            }
        }
        __syncthreads();
    }

    // ---- fused FC head: final h2 in sH[1] (t=511 wrote buf 1) ----
    const __half* hf = sH[1];
    const int r = lane;   // fc1 neuron 0..31
    #pragma unroll
    for (int rep = 0; rep < 2; rep++){
        int m = w * 2 + rep;
        float s = fc1b[r];
        #pragma unroll 8
        for (int k = 0; k < 64; k++)
            s += __half2float(hf[m * 72 + k]) * fc1w[r * 64 + k];
        float z = fmaxf(s, 0.f) * fc2w[r];
        #pragma unroll
        for (int off = 16; off > 0; off >>= 1)
            z += __shfl_xor_sync(0xffffffffu, z, off);
        if (r == 0) out[b0 + m] = sigf(z + fc2b[0]);
    }
}

// =====================================================================
extern "C" void kernel_launch(void* const* d_in, const int* in_sizes, int n_in,
                              void* d_out, int out_size)
{
    const float* X     = (const float*)d_in[0];
    const float* W1_ih = (const float*)d_in[1];
    const float* W1_hh = (const float*)d_in[2];
    const float* b1_ih = (const float*)d_in[3];
    const float* b1_hh = (const float*)d_in[4];
    const float* W2_ih = (const float*)d_in[5];
    const float* W2_hh = (const float*)d_in[6];
    const float* b2_ih = (const float*)d_in[7];
    const float* b2_hh = (const float*)d_in[8];
    const float* fc1w  = (const float*)d_in[9];
    const float* fc1b  = (const float*)d_in[10];
    const float* fc2w  = (const float*)d_in[11];
    const float* fc2b  = (const float*)d_in[12];
    float* out = (float*)d_out;

    const int g1_smem = (100 * 132 + 100 * 68) * 4;   // 80000 B
    const int g2_smem = (128 * 132 + 128 * 68) * 4;   // 102400 B

    cudaFuncSetAttribute(gemm1_kernel, cudaFuncAttributeMaxDynamicSharedMemorySize, g1_smem);
    cudaFuncSetAttribute(gemm2_kernel, cudaFuncAttributeMaxDynamicSharedMemorySize, g2_smem);

    gemm1_kernel<<<dim3(8, 4096), 256, g1_smem>>>(X, W1_ih, b1_ih, b1_hh);
    rec1_kernel<<<64, 256>>>(W1_hh);
    gemm2_kernel<<<dim3(4, 4096), 256, g2_smem>>>(W2_ih, b2_ih, b2_hh);
    rec2_kernel<<<64, 256>>>(W2_hh, fc1w, fc1b, fc2w, fc2b, out);
}

// round 4
// speedup vs baseline: 1.7264x; 1.7264x over previous
#include <cuda_runtime.h>
#include <cuda_fp16.h>
#include <cstdint>

typedef unsigned long long ull;

// ---------------- scratch (static device allocations; no cudaMalloc) ----------------
__device__ __half g_xw1h[268435456];  // [T=512][B=1024][n=512] fp16, n = j*4+q  (512 MiB)
__device__ __half g_xw2h[134217728];  // [T=512][B=1024][n=256] fp16, n = j*4+q  (256 MiB)
__device__ __half g_hs1[67108864];    // [T=512][B=1024][128]   fp16             (128 MiB)

// ---------------- helpers ----------------
__device__ __forceinline__ ull pack2(float lo, float hi){
    ull r; asm("mov.b64 %0, {%1, %2};" : "=l"(r) : "f"(lo), "f"(hi)); return r;
}
__device__ __forceinline__ float2 unpack2(ull v){
    float2 f; asm("mov.b64 {%0, %1}, %2;" : "=f"(f.x), "=f"(f.y) : "l"(v)); return f;
}
__device__ __forceinline__ ull ffma2(ull a, ull b, ull c){
    ull d; asm("fma.rn.f32x2 %0, %1, %2, %3;" : "=l"(d) : "l"(a), "l"(b), "l"(c)); return d;
}
__device__ __forceinline__ float sigf(float x){ return 1.f / (1.f + __expf(-x)); }
__device__ __forceinline__ float tanh_f(float x){ return 1.f - 2.f / (__expf(2.f * x) + 1.f); }

__device__ __forceinline__ void mma16816(float& c0, float& c1, float& c2, float& c3,
                                         uint32_t a0, uint32_t a1, uint32_t a2, uint32_t a3,
                                         uint32_t b0, uint32_t b1){
    asm("mma.sync.aligned.m16n8k16.row.col.f32.f16.f16.f32 "
        "{%0,%1,%2,%3}, {%4,%5,%6,%7}, {%8,%9}, {%0,%1,%2,%3};"
        : "+f"(c0), "+f"(c1), "+f"(c2), "+f"(c3)
        : "r"(a0), "r"(a1), "r"(a2), "r"(a3), "r"(b0), "r"(b1));
}

// =====================================================================
// GEMM1 (tensor core): xw1[(t,b), n] = X @ W1_ih^T + bias (fp16 out)
// n = j*4+q, gate row g = q*128+j. CTA tile 128x128, K=100 padded to 112.
// B staged n-major in SMEM -> B frags are 2 conflict-free LDS.32.
// =====================================================================
__global__ void __launch_bounds__(256) gemm1_tc(
    const float* __restrict__ X, const float* __restrict__ W,
    const float* __restrict__ bih, const float* __restrict__ bhh)
{
    extern __shared__ __half sm[];
    __half* sA = sm;               // [128][120]  (rows of X, fp16)
    __half* sB = sm + 128 * 120;   // [128][120]  n-major (rows = output cols)
    const int tid = threadIdx.x;
    const int cb = blockIdx.x;     // n-block (0..3)
    const int rb = blockIdx.y;     // m-block (0..4095)
    const int r0 = rb * 128;
    const int n0c = cb * 128;

    const float* Ab = X + (size_t)r0 * 100;
    for (int idx = tid; idx < 12800; idx += 256){
        int i = idx / 100, e = idx - i * 100;
        sA[i * 120 + e] = __float2half(Ab[idx]);
    }
    for (int idx = tid; idx < 1536; idx += 256){
        int i = idx / 12, e = idx - i * 12;
        sA[i * 120 + 100 + e] = __float2half(0.f);
    }
    for (int idx = tid; idx < 12800; idx += 256){
        int nn = idx / 100, k = idx - nn * 100;
        int n = n0c + nn, j = n >> 2, q = n & 3, g = q * 128 + j;
        sB[nn * 120 + k] = __float2half(W[g * 100 + k]);
    }
    for (int idx = tid; idx < 1536; idx += 256){
        int nn = idx / 12, k = idx - nn * 12;
        sB[nn * 120 + 100 + k] = __float2half(0.f);
    }
    __syncthreads();

    const int w = tid >> 5, lane = tid & 31;
    const int wm = w >> 2, wn = w & 3;          // 2 x 4 warp grid (m64 x n32)
    const int m0w = wm * 64, n0w = wn * 32;
    const int gp = lane >> 2, tig = lane & 3;

    float acc[4][4][4];
    #pragma unroll
    for (int mt = 0; mt < 4; mt++)
        #pragma unroll
        for (int nt = 0; nt < 4; nt++){
            acc[mt][nt][0]=0.f; acc[mt][nt][1]=0.f; acc[mt][nt][2]=0.f; acc[mt][nt][3]=0.f;
        }

    float bias[4][2];
    #pragma unroll
    for (int nt = 0; nt < 4; nt++){
        int n = n0c + n0w + nt * 8 + 2 * tig;
        int j0 = n >> 2, q0 = n & 3;       bias[nt][0] = bih[q0*128+j0] + bhh[q0*128+j0];
        int n1 = n + 1;
        int j1 = n1 >> 2, q1 = n1 & 3;     bias[nt][1] = bih[q1*128+j1] + bhh[q1*128+j1];
    }

    #pragma unroll
    for (int kt = 0; kt < 7; kt++){
        const int k0 = kt * 16;
        uint32_t af[4][4];
        #pragma unroll
        for (int mt = 0; mt < 4; mt++){
            const __half* ap = sA + (m0w + mt * 16 + gp) * 120 + k0 + 2 * tig;
            af[mt][0] = *(const uint32_t*)ap;
            af[mt][1] = *(const uint32_t*)(ap + 8 * 120);
            af[mt][2] = *(const uint32_t*)(ap + 8);
            af[mt][3] = *(const uint32_t*)(ap + 8 * 120 + 8);
        }
        #pragma unroll
        for (int nt = 0; nt < 4; nt++){
            const __half* bp = sB + (n0w + nt * 8 + gp) * 120 + k0 + 2 * tig;
            uint32_t b0 = *(const uint32_t*)bp;
            uint32_t b1 = *(const uint32_t*)(bp + 8);
            #pragma unroll
            for (int mt = 0; mt < 4; mt++)
                mma16816(acc[mt][nt][0], acc[mt][nt][1], acc[mt][nt][2], acc[mt][nt][3],
                         af[mt][0], af[mt][1], af[mt][2], af[mt][3], b0, b1);
        }
    }

    // epilogue: add bias, cvt fp16, store to permuted row (t*1024+b)
    #pragma unroll
    for (int mt = 0; mt < 4; mt++){
        int ra = m0w + mt * 16 + gp;
        int r  = r0 + ra;
        size_t rpa = ((size_t)(r & 511) * 1024 + (r >> 9)) * 512;
        int r2 = r + 8;
        size_t rpb = ((size_t)(r2 & 511) * 1024 + (r2 >> 9)) * 512;
        #pragma unroll
        for (int nt = 0; nt < 4; nt++){
            int n = n0c + n0w + nt * 8 + 2 * tig;
            __half2 v0 = __floats2half2_rn(acc[mt][nt][0] + bias[nt][0], acc[mt][nt][1] + bias[nt][1]);
            __half2 v1 = __floats2half2_rn(acc[mt][nt][2] + bias[nt][0], acc[mt][nt][3] + bias[nt][1]);
            *(__half2*)(g_xw1h + rpa + n) = v0;
            *(__half2*)(g_xw1h + rpb + n) = v1;
        }
    }
}

// =====================================================================
// GEMM2 (tensor core): xw2 = hs1 @ W2_ih^T + bias (fp16 out), K=128.
// Rows of hs1 are already (t*1024+b) order -> identity row mapping.
// =====================================================================
__global__ void __launch_bounds__(256) gemm2_tc(
    const float* __restrict__ W, const float* __restrict__ bih, const float* __restrict__ bhh)
{
    extern __shared__ __half sm[];
    __half* sA = sm;               // [128][136]
    __half* sB = sm + 128 * 136;   // [128][136]  n-major
    const int tid = threadIdx.x;
    const int cb = blockIdx.x;     // 0..1
    const int rb = blockIdx.y;     // 0..4095
    const int r0 = rb * 128;
    const int n0c = cb * 128;

    for (int idx = tid; idx < 2048; idx += 256){
        int row = idx >> 4, c8 = (idx & 15) * 8;
        *(int4*)(sA + row * 136 + c8) = *(const int4*)(g_hs1 + ((size_t)(r0 + row)) * 128 + c8);
    }
    for (int idx = tid; idx < 16384; idx += 256){
        int nn = idx >> 7, k = idx & 127;
        int n = n0c + nn, j = n >> 2, q = n & 3, g = q * 64 + j;
        sB[nn * 136 + k] = __float2half(W[g * 128 + k]);
    }
    __syncthreads();

    const int w = tid >> 5, lane = tid & 31;
    const int wm = w >> 2, wn = w & 3;
    const int m0w = wm * 64, n0w = wn * 32;
    const int gp = lane >> 2, tig = lane & 3;

    float acc[4][4][4];
    #pragma unroll
    for (int mt = 0; mt < 4; mt++)
        #pragma unroll
        for (int nt = 0; nt < 4; nt++){
            acc[mt][nt][0]=0.f; acc[mt][nt][1]=0.f; acc[mt][nt][2]=0.f; acc[mt][nt][3]=0.f;
        }

    float bias[4][2];
    #pragma unroll
    for (int nt = 0; nt < 4; nt++){
        int n = n0c + n0w + nt * 8 + 2 * tig;
        int j0 = n >> 2, q0 = n & 3;       bias[nt][0] = bih[q0*64+j0] + bhh[q0*64+j0];
        int n1 = n + 1;
        int j1 = n1 >> 2, q1 = n1 & 3;     bias[nt][1] = bih[q1*64+j1] + bhh[q1*64+j1];
    }

    #pragma unroll
    for (int kt = 0; kt < 8; kt++){
        const int k0 = kt * 16;
        uint32_t af[4][4];
        #pragma unroll
        for (int mt = 0; mt < 4; mt++){
            const __half* ap = sA + (m0w + mt * 16 + gp) * 136 + k0 + 2 * tig;
            af[mt][0] = *(const uint32_t*)ap;
            af[mt][1] = *(const uint32_t*)(ap + 8 * 136);
            af[mt][2] = *(const uint32_t*)(ap + 8);
            af[mt][3] = *(const uint32_t*)(ap + 8 * 136 + 8);
        }
        #pragma unroll
        for (int nt = 0; nt < 4; nt++){
            const __half* bp = sB + (n0w + nt * 8 + gp) * 136 + k0 + 2 * tig;
            uint32_t b0 = *(const uint32_t*)bp;
            uint32_t b1 = *(const uint32_t*)(bp + 8);
            #pragma unroll
            for (int mt = 0; mt < 4; mt++)
                mma16816(acc[mt][nt][0], acc[mt][nt][1], acc[mt][nt][2], acc[mt][nt][3],
                         af[mt][0], af[mt][1], af[mt][2], af[mt][3], b0, b1);
        }
    }

    #pragma unroll
    for (int mt = 0; mt < 4; mt++){
        int ra = m0w + mt * 16 + gp;
        size_t rpa = (size_t)(r0 + ra) * 256;
        size_t rpb = (size_t)(r0 + ra + 8) * 256;
        #pragma unroll
        for (int nt = 0; nt < 4; nt++){
            int n = n0c + n0w + nt * 8 + 2 * tig;
            __half2 v0 = __floats2half2_rn(acc[mt][nt][0] + bias[nt][0], acc[mt][nt][1] + bias[nt][1]);
            __half2 v1 = __floats2half2_rn(acc[mt][nt][2] + bias[nt][0], acc[mt][nt][3] + bias[nt][1]);
            *(__half2*)(g_xw2h + rpa + n) = v0;
            *(__half2*)(g_xw2h + rpb + n) = v1;
        }
    }
}

// =====================================================================
// REC1 (proven R1 scalar FFMA2): 128 CTAs x 8 batch rows, 256 threads.
// =====================================================================
__global__ void __launch_bounds__(256) rec1_kernel(const float* __restrict__ Whh)
{
    extern __shared__ char smc[];
    __half* sW = (__half*)smc;                 // [128][128][4] = 128 KiB
    float*  sH = (float*)(smc + 131072);       // [k=128][m=8]  = 4 KiB
    const int tid = threadIdx.x;
    const int b0 = blockIdx.x * 8;

    for (int idx = tid; idx < 65536; idx += 256){
        int k = idx & 127;
        int j = (idx >> 7) & 127;
        int q = idx >> 14;
        sW[(k * 128 + j) * 4 + q] = __float2half(Whh[(q * 128 + j) * 128 + k]);
    }
    for (int i = tid; i < 1024; i += 256) sH[i] = 0.f;
    __syncthreads();

    const int j = tid & 127, mh = tid >> 7;
    float cst[4] = {0.f, 0.f, 0.f, 0.f};
    const uint2* wp  = (const uint2*)sW + j;
    const float* hp0 = sH + mh * 4;

    for (int t = 0; t < 512; t++){
        size_t base = ((size_t)t * 1024 + b0) * 512 + (size_t)j * 4;
        float4 xv[2][2];
        #pragma unroll
        for (int p = 0; p < 2; p++){
            #pragma unroll
            for (int L = 0; L < 2; L++){
                int m = mh * 4 + p * 2 + L;
                ull raw = *(const ull*)(g_xw1h + base + (size_t)m * 512);
                const __half2* hp = (const __half2*)&raw;
                float2 f01 = __half22float2(hp[0]);
                float2 f23 = __half22float2(hp[1]);
                xv[p][L] = make_float4(f01.x, f01.y, f23.x, f23.y);
            }
        }

        ull acc[4][2] = {{0ull,0ull},{0ull,0ull},{0ull,0ull},{0ull,0ull}};
        #pragma unroll 4
        for (int k = 0; k < 128; k++){
            uint2 wraw = wp[k * 128];
            float2 w01 = __half22float2(*(const __half2*)&wraw.x);
            float2 w23 = __half22float2(*(const __half2*)&wraw.y);
            ulonglong2 hv = *(const ulonglong2*)(hp0 + k * 8);
            ull W0 = pack2(w01.x, w01.x);
            ull W1 = pack2(w01.y, w01.y);
            ull W2 = pack2(w23.x, w23.x);
            ull W3 = pack2(w23.y, w23.y);
            acc[0][0]=ffma2(W0,hv.x,acc[0][0]); acc[0][1]=ffma2(W0,hv.y,acc[0][1]);
            acc[1][0]=ffma2(W1,hv.x,acc[1][0]); acc[1][1]=ffma2(W1,hv.y,acc[1][1]);
            acc[2][0]=ffma2(W2,hv.x,acc[2][0]); acc[2][1]=ffma2(W2,hv.y,acc[2][1]);
            acc[3][0]=ffma2(W3,hv.x,acc[3][0]); acc[3][1]=ffma2(W3,hv.y,acc[3][1]);
        }
        __syncthreads();

        #pragma unroll
        for (int p = 0; p < 2; p++){
            float2 gi_ = unpack2(acc[0][p]);
            float2 gf_ = unpack2(acc[1][p]);
            float2 gg_ = unpack2(acc[2][p]);
            float2 go_ = unpack2(acc[3][p]);
            #pragma unroll
            for (int L = 0; L < 2; L++){
                const float4 x4 = xv[p][L];
                float ai = (L ? gi_.y : gi_.x) + x4.x;
                float af = (L ? gf_.y : gf_.x) + x4.y;
                float ag = (L ? gg_.y : gg_.x) + x4.z;
                float ao = (L ? go_.y : go_.x) + x4.w;
                float iv = sigf(ai), fv = sigf(af), gv = tanh_f(ag), ov = sigf(ao);
                int ci = p * 2 + L;
                float cn = fv * cst[ci] + iv * gv;
                cst[ci] = cn;
                float h = ov * tanh_f(cn);
                int m = mh * 4 + p * 2 + L;
                sH[j * 8 + m] = h;
                g_hs1[((size_t)t * 1024 + (b0 + m)) * 128 + j] = __float2half(h);
            }
        }
        __syncthreads();
    }
}

// =====================================================================
// REC2 (proven R1 scalar FFMA2) + fused FC head. 128 CTAs x 8 rows.
// =====================================================================
__global__ void __launch_bounds__(256) rec2_kernel(
    const float* __restrict__ Whh,
    const float* __restrict__ fc1w, const float* __restrict__ fc1b,
    const float* __restrict__ fc2w, const float* __restrict__ fc2b,
    float* __restrict__ out)
{
    extern __shared__ char smc[];
    __half* sW = (__half*)smc;                 // [64][64][4] = 32 KiB
    float*  sH = (float*)(smc + 32768);        // [k=64][m=8] = 2 KiB
    const int tid = threadIdx.x;
    const int b0 = blockIdx.x * 8;

    for (int idx = tid; idx < 16384; idx += 256){
        int k = idx & 63;
        int j = (idx >> 6) & 63;
        int q = idx >> 12;
        sW[(k * 64 + j) * 4 + q] = __float2half(Whh[(q * 64 + j) * 64 + k]);
    }
    for (int i = tid; i < 512; i += 256) sH[i] = 0.f;
    __syncthreads();

    const int j = tid & 63, ph = tid >> 6;
    const int m0 = ph * 2;
    float cst[2] = {0.f, 0.f};
    const uint2* wp  = (const uint2*)sW + j;
    const float* hp0 = sH + m0;

    for (int t = 0; t < 512; t++){
        size_t base = ((size_t)t * 1024 + b0) * 256 + (size_t)j * 4;
        float4 xv0, xv1;
        {
            ull raw0 = *(const ull*)(g_xw2h + base + (size_t)m0 * 256);
            ull raw1 = *(const ull*)(g_xw2h + base + (size_t)(m0 + 1) * 256);
            const __half2* h0 = (const __half2*)&raw0;
            const __half2* h1 = (const __half2*)&raw1;
            float2 a01 = __half22float2(h0[0]), a23 = __half22float2(h0[1]);
            float2 b01 = __half22float2(h1[0]), b23 = __half22float2(h1[1]);
            xv0 = make_float4(a01.x, a01.y, a23.x, a23.y);
            xv1 = make_float4(b01.x, b01.y, b23.x, b23.y);
        }

        ull acc[4] = {0ull, 0ull, 0ull, 0ull};
        #pragma unroll 4
        for (int k = 0; k < 64; k++){
            uint2 wraw = wp[k * 64];
            float2 w01 = __half22float2(*(const __half2*)&wraw.x);
            float2 w23 = __half22float2(*(const __half2*)&wraw.y);
            ull hv = *(const ull*)(hp0 + k * 8);
            acc[0] = ffma2(pack2(w01.x, w01.x), hv, acc[0]);
            acc[1] = ffma2(pack2(w01.y, w01.y), hv, acc[1]);
            acc[2] = ffma2(pack2(w23.x, w23.x), hv, acc[2]);
            acc[3] = ffma2(pack2(w23.y, w23.y), hv, acc[3]);
        }
        __syncthreads();

        float2 gi_ = unpack2(acc[0]);
        float2 gf_ = unpack2(acc[1]);
        float2 gg_ = unpack2(acc[2]);
        float2 go_ = unpack2(acc[3]);
        #pragma unroll
        for (int L = 0; L < 2; L++){
            const float4 x4 = L ? xv1 : xv0;
            float ai = (L ? gi_.y : gi_.x) + x4.x;
            float af = (L ? gf_.y : gf_.x) + x4.y;
            float ag = (L ? gg_.y : gg_.x) + x4.z;
            float ao = (L ? go_.y : go_.x) + x4.w;
            float iv = sigf(ai), fv = sigf(af), gv = tanh_f(ag), ov = sigf(ao);
            float cn = fv * cst[L] + iv * gv;
            cst[L] = cn;
            sH[j * 8 + m0 + L] = ov * tanh_f(cn);
        }
        __syncthreads();
    }

    // Fused FC head on final h2 (in sH[k][m]): warp w handles batch row m=w.
    const int m = tid >> 5, r = tid & 31;
    float s = fc1b[r];
    #pragma unroll 8
    for (int k = 0; k < 64; k++)
        s += sH[k * 8 + m] * fc1w[r * 64 + k];
    float z = fmaxf(s, 0.f) * fc2w[r];
    #pragma unroll
    for (int off = 16; off > 0; off >>= 1)
        z += __shfl_xor_sync(0xffffffffu, z, off);
    if (r == 0) out[b0 + m] = sigf(z + fc2b[0]);
}

// =====================================================================
extern "C" void kernel_launch(void* const* d_in, const int* in_sizes, int n_in,
                              void* d_out, int out_size)
{
    const float* X     = (const float*)d_in[0];
    const float* W1_ih = (const float*)d_in[1];
    const float* W1_hh = (const float*)d_in[2];
    const float* b1_ih = (const float*)d_in[3];
    const float* b1_hh = (const float*)d_in[4];
    const float* W2_ih = (const float*)d_in[5];
    const float* W2_hh = (const float*)d_in[6];
    const float* b2_ih = (const float*)d_in[7];
    const float* b2_hh = (const float*)d_in[8];
    const float* fc1w  = (const float*)d_in[9];
    const float* fc1b  = (const float*)d_in[10];
    const float* fc2w  = (const float*)d_in[11];
    const float* fc2b  = (const float*)d_in[12];
    float* out = (float*)d_out;

    const int g1_smem = 2 * 128 * 120 * 2;            // 61440 B
    const int g2_smem = 2 * 128 * 136 * 2;            // 69632 B
    const int r1_smem = 131072 + 4096;                // 135168 B
    const int r2_smem = 32768 + 2048;                 // 34816 B

    cudaFuncSetAttribute(gemm1_tc,   cudaFuncAttributeMaxDynamicSharedMemorySize, g1_smem);
    cudaFuncSetAttribute(gemm2_tc,   cudaFuncAttributeMaxDynamicSharedMemorySize, g2_smem);
    cudaFuncSetAttribute(rec1_kernel, cudaFuncAttributeMaxDynamicSharedMemorySize, r1_smem);
    cudaFuncSetAttribute(rec2_kernel, cudaFuncAttributeMaxDynamicSharedMemorySize, r2_smem);

    gemm1_tc<<<dim3(4, 4096), 256, g1_smem>>>(X, W1_ih, b1_ih, b1_hh);
    rec1_kernel<<<128, 256, r1_smem>>>(W1_hh);
    gemm2_tc<<<dim3(2, 4096), 256, g2_smem>>>(W2_ih, b2_ih, b2_hh);
    rec2_kernel<<<128, 256, r2_smem>>>(W2_hh, fc1w, fc1b, fc2w, fc2b, out);
}

// round 5
// speedup vs baseline: 1.8343x; 1.0625x over previous
#include <cuda_runtime.h>
#include <cuda_fp16.h>
#include <cstdint>

typedef unsigned long long ull;

// ---------------- scratch (static device allocations; no cudaMalloc) ----------------
__device__ __half g_xw1h[268435456];  // [T=512][B=1024][n=512] fp16, n = j*4+q  (512 MiB)
__device__ __half g_xw2h[134217728];  // [T=512][B=1024][n=256] fp16, n = j*4+q  (256 MiB)
__device__ __half g_hs1[67108864];    // [T=512][B=1024][128]   fp16             (128 MiB)

// preconverted weights (fp16) + combined biases (fp32)
__device__ __half g_w1[512 * 112];    // W1_ih n-major: [n][k], k padded 100->112 w/ zeros
__device__ __half g_w2[256 * 128];    // W2_ih n-major: [n][k=128]
__device__ __half g_w1hh[65536];      // rec1 layout: [(k*128+j)*4+q]
__device__ __half g_w2hh[16384];      // rec2 layout: [(k*64+j)*4+q]
__device__ float  g_b1[512];          // b1_ih+b1_hh at n = j*4+q
__device__ float  g_b2[256];          // b2_ih+b2_hh at n = j*4+q

// ---------------- helpers ----------------
__device__ __forceinline__ ull pack2(float lo, float hi){
    ull r; asm("mov.b64 %0, {%1, %2};" : "=l"(r) : "f"(lo), "f"(hi)); return r;
}
__device__ __forceinline__ float2 unpack2(ull v){
    float2 f; asm("mov.b64 {%0, %1}, %2;" : "=f"(f.x), "=f"(f.y) : "l"(v)); return f;
}
__device__ __forceinline__ ull ffma2(ull a, ull b, ull c){
    ull d; asm("fma.rn.f32x2 %0, %1, %2, %3;" : "=l"(d) : "l"(a), "l"(b), "l"(c)); return d;
}
__device__ __forceinline__ float sigf(float x){ return 1.f / (1.f + __expf(-x)); }
__device__ __forceinline__ float tanh_f(float x){ return 1.f - 2.f / (__expf(2.f * x) + 1.f); }

__device__ __forceinline__ void mma16816(float& c0, float& c1, float& c2, float& c3,
                                         uint32_t a0, uint32_t a1, uint32_t a2, uint32_t a3,
                                         uint32_t b0, uint32_t b1){
    asm("mma.sync.aligned.m16n8k16.row.col.f32.f16.f16.f32 "
        "{%0,%1,%2,%3}, {%4,%5,%6,%7}, {%8,%9}, {%0,%1,%2,%3};"
        : "+f"(c0), "+f"(c1), "+f"(c2), "+f"(c3)
        : "r"(a0), "r"(a1), "r"(a2), "r"(a3), "r"(b0), "r"(b1));
}

// =====================================================================
// PREP: one-shot weight conversion (runs in ~10us, amortized)
// =====================================================================
__global__ void __launch_bounds__(256) prep_kernel(
    const float* __restrict__ W1_ih, const float* __restrict__ W1_hh,
    const float* __restrict__ b1_ih, const float* __restrict__ b1_hh,
    const float* __restrict__ W2_ih, const float* __restrict__ W2_hh,
    const float* __restrict__ b2_ih, const float* __restrict__ b2_hh)
{
    const int tid = blockIdx.x * blockDim.x + threadIdx.x;
    const int stride = gridDim.x * blockDim.x;
    for (int i = tid; i < 512 * 112; i += stride){
        int n = i / 112, k = i - n * 112;
        int j = n >> 2, q = n & 3;
        g_w1[i] = __float2half(k < 100 ? W1_ih[(q * 128 + j) * 100 + k] : 0.f);
    }
    for (int i = tid; i < 256 * 128; i += stride){
        int n = i >> 7, k = i & 127;
        int j = n >> 2, q = n & 3;
        g_w2[i] = __float2half(W2_ih[(q * 64 + j) * 128 + k]);
    }
    for (int i = tid; i < 65536; i += stride){
        int q = i & 3, j = (i >> 2) & 127, k = i >> 9;
        g_w1hh[i] = __float2half(W1_hh[(q * 128 + j) * 128 + k]);
    }
    for (int i = tid; i < 16384; i += stride){
        int q = i & 3, j = (i >> 2) & 63, k = i >> 8;
        g_w2hh[i] = __float2half(W2_hh[(q * 64 + j) * 64 + k]);
    }
    for (int i = tid; i < 512; i += stride){
        int j = i >> 2, q = i & 3;
        g_b1[i] = b1_ih[q * 128 + j] + b1_hh[q * 128 + j];
    }
    for (int i = tid; i < 256; i += stride){
        int j = i >> 2, q = i & 3;
        g_b2[i] = b2_ih[q * 64 + j] + b2_hh[q * 64 + j];
    }
}

// =====================================================================
// GEMM1 (tensor core): xw1[(t,b), n] = X @ W1_ih^T + bias (fp16 out)
// CTA tile 128x128, K=112 (padded). Vectorized fills, staged epilogue.
// =====================================================================
__global__ void __launch_bounds__(256) gemm1_tc(const float* __restrict__ X)
{
    extern __shared__ __half sm[];
    __half* sA = sm;               // [128][120]
    __half* sB = sm + 128 * 120;   // [128][120] n-major
    const int tid = threadIdx.x;
    const int cb = blockIdx.x;     // 0..3
    const int rb = blockIdx.y;     // 0..4095
    const int r0 = rb * 128;
    const int n0c = cb * 128;

    // A fill: 128 rows x 100 floats via float4 (3200 float4)
    const float4* X4 = (const float4*)(X + (size_t)r0 * 100);
    for (int idx = tid; idx < 3200; idx += 256){
        int row = idx / 25, c4 = idx - row * 25;
        float4 v = X4[row * 25 + c4];
        __half2 h0 = __floats2half2_rn(v.x, v.y);
        __half2 h1 = __floats2half2_rn(v.z, v.w);
        ull packed = ((ull)(*(uint32_t*)&h1) << 32) | (*(uint32_t*)&h0);
        *(ull*)(sA + row * 120 + c4 * 4) = packed;
    }
    // zero k=100..112
    for (int idx = tid; idx < 768; idx += 256){
        int row = idx / 6, e = (idx - row * 6) * 2;
        *(uint32_t*)(sA + row * 120 + 100 + e) = 0u;
    }
    // B fill: int4 copies from preconverted g_w1 (14 int4 per n-row)
    for (int idx = tid; idx < 1792; idx += 256){
        int nn = idx / 14, c8 = (idx - nn * 14) * 8;
        *(int4*)(sB + nn * 120 + c8) = *(const int4*)(g_w1 + (size_t)(n0c + nn) * 112 + c8);
    }
    __syncthreads();

    const int w = tid >> 5, lane = tid & 31;
    const int wm = w >> 2, wn = w & 3;          // 2 x 4 warps (m64 x n32)
    const int m0w = wm * 64, n0w = wn * 32;
    const int gp = lane >> 2, tig = lane & 3;

    float acc[4][4][4];
    #pragma unroll
    for (int mt = 0; mt < 4; mt++)
        #pragma unroll
        for (int nt = 0; nt < 4; nt++){
            acc[mt][nt][0]=0.f; acc[mt][nt][1]=0.f; acc[mt][nt][2]=0.f; acc[mt][nt][3]=0.f;
        }

    float2 bias[4];
    #pragma unroll
    for (int nt = 0; nt < 4; nt++)
        bias[nt] = *(const float2*)(g_b1 + n0c + n0w + nt * 8 + 2 * tig);

    #pragma unroll
    for (int kt = 0; kt < 7; kt++){
        const int k0 = kt * 16;
        uint32_t af[4][4];
        #pragma unroll
        for (int mt = 0; mt < 4; mt++){
            const __half* ap = sA + (m0w + mt * 16 + gp) * 120 + k0 + 2 * tig;
            af[mt][0] = *(const uint32_t*)ap;
            af[mt][1] = *(const uint32_t*)(ap + 8 * 120);
            af[mt][2] = *(const uint32_t*)(ap + 8);
            af[mt][3] = *(const uint32_t*)(ap + 8 * 120 + 8);
        }
        #pragma unroll
        for (int nt = 0; nt < 4; nt++){
            const __half* bp = sB + (n0w + nt * 8 + gp) * 120 + k0 + 2 * tig;
            uint32_t b0 = *(const uint32_t*)bp;
            uint32_t b1 = *(const uint32_t*)(bp + 8);
            #pragma unroll
            for (int mt = 0; mt < 4; mt++)
                mma16816(acc[mt][nt][0], acc[mt][nt][1], acc[mt][nt][2], acc[mt][nt][3],
                         af[mt][0], af[mt][1], af[mt][2], af[mt][3], b0, b1);
        }
    }

    // stage epilogue in SMEM (stride 136 halfs), then coalesced int4 stores
    __syncthreads();
    __half* stg = sm;   // reuse, [128][136]
    #pragma unroll
    for (int mt = 0; mt < 4; mt++){
        int ra = m0w + mt * 16 + gp;
        #pragma unroll
        for (int nt = 0; nt < 4; nt++){
            int nl = n0w + nt * 8 + 2 * tig;
            __half2 v0 = __floats2half2_rn(acc[mt][nt][0] + bias[nt].x, acc[mt][nt][1] + bias[nt].y);
            __half2 v1 = __floats2half2_rn(acc[mt][nt][2] + bias[nt].x, acc[mt][nt][3] + bias[nt].y);
            *(__half2*)(stg + ra * 136 + nl) = v0;
            *(__half2*)(stg + (ra + 8) * 136 + nl) = v1;
        }
    }
    __syncthreads();
    #pragma unroll
    for (int i = 0; i < 8; i++){
        int idx = tid + i * 256;
        int row = idx >> 4, col8 = (idx & 15) * 8;
        int r = r0 + row;                              // r = b*512 + t
        size_t orow = (size_t)(r & 511) * 1024 + (r >> 9);
        *(int4*)(g_xw1h + orow * 512 + n0c + col8) = *(const int4*)(stg + row * 136 + col8);
    }
}

// =====================================================================
// GEMM2 (tensor core): xw2 = hs1 @ W2_ih^T + bias (fp16 out), K=128.
// =====================================================================
__global__ void __launch_bounds__(256) gemm2_tc()
{
    extern __shared__ __half sm[];
    __half* sA = sm;               // [128][136]
    __half* sB = sm + 128 * 136;   // [128][136] n-major
    const int tid = threadIdx.x;
    const int cb = blockIdx.x;     // 0..1
    const int rb = blockIdx.y;     // 0..4095
    const int r0 = rb * 128;
    const int n0c = cb * 128;

    for (int idx = tid; idx < 2048; idx += 256){
        int row = idx >> 4, c8 = (idx & 15) * 8;
        *(int4*)(sA + row * 136 + c8) = *(const int4*)(g_hs1 + (size_t)(r0 + row) * 128 + c8);
    }
    for (int idx = tid; idx < 2048; idx += 256){
        int nn = idx >> 4, c8 = (idx & 15) * 8;
        *(int4*)(sB + nn * 136 + c8) = *(const int4*)(g_w2 + (size_t)(n0c + nn) * 128 + c8);
    }
    __syncthreads();

    const int w = tid >> 5, lane = tid & 31;
    const int wm = w >> 2, wn = w & 3;
    const int m0w = wm * 64, n0w = wn * 32;
    const int gp = lane >> 2, tig = lane & 3;

    float acc[4][4][4];
    #pragma unroll
    for (int mt = 0; mt < 4; mt++)
        #pragma unroll
        for (int nt = 0; nt < 4; nt++){
            acc[mt][nt][0]=0.f; acc[mt][nt][1]=0.f; acc[mt][nt][2]=0.f; acc[mt][nt][3]=0.f;
        }

    float2 bias[4];
    #pragma unroll
    for (int nt = 0; nt < 4; nt++)
        bias[nt] = *(const float2*)(g_b2 + n0c + n0w + nt * 8 + 2 * tig);

    #pragma unroll
    for (int kt = 0; kt < 8; kt++){
        const int k0 = kt * 16;
        uint32_t af[4][4];
        #pragma unroll
        for (int mt = 0; mt < 4; mt++){
            const __half* ap = sA + (m0w + mt * 16 + gp) * 136 + k0 + 2 * tig;
            af[mt][0] = *(const uint32_t*)ap;
            af[mt][1] = *(const uint32_t*)(ap + 8 * 136);
            af[mt][2] = *(const uint32_t*)(ap + 8);
            af[mt][3] = *(const uint32_t*)(ap + 8 * 136 + 8);
        }
        #pragma unroll
        for (int nt = 0; nt < 4; nt++){
            const __half* bp = sB + (n0w + nt * 8 + gp) * 136 + k0 + 2 * tig;
            uint32_t b0 = *(const uint32_t*)bp;
            uint32_t b1 = *(const uint32_t*)(bp + 8);
            #pragma unroll
            for (int mt = 0; mt < 4; mt++)
                mma16816(acc[mt][nt][0], acc[mt][nt][1], acc[mt][nt][2], acc[mt][nt][3],
                         af[mt][0], af[mt][1], af[mt][2], af[mt][3], b0, b1);
        }
    }

    __syncthreads();
    __half* stg = sm;   // reuse, [128][136]
    #pragma unroll
    for (int mt = 0; mt < 4; mt++){
        int ra = m0w + mt * 16 + gp;
        #pragma unroll
        for (int nt = 0; nt < 4; nt++){
            int nl = n0w + nt * 8 + 2 * tig;
            __half2 v0 = __floats2half2_rn(acc[mt][nt][0] + bias[nt].x, acc[mt][nt][1] + bias[nt].y);
            __half2 v1 = __floats2half2_rn(acc[mt][nt][2] + bias[nt].x, acc[mt][nt][3] + bias[nt].y);
            *(__half2*)(stg + ra * 136 + nl) = v0;
            *(__half2*)(stg + (ra + 8) * 136 + nl) = v1;
        }
    }
    __syncthreads();
    #pragma unroll
    for (int i = 0; i < 8; i++){
        int idx = tid + i * 256;
        int row = idx >> 4, col8 = (idx & 15) * 8;
        *(int4*)(g_xw2h + (size_t)(r0 + row) * 256 + n0c + col8) = *(const int4*)(stg + row * 136 + col8);
    }
}

// =====================================================================
// REC1 (scalar FFMA2, proven): 128 CTAs x 8 batch rows, 256 threads.
// =====================================================================
__global__ void __launch_bounds__(256) rec1_kernel()
{
    extern __shared__ char smc[];
    __half* sW = (__half*)smc;                 // [128][128][4] = 128 KiB
    float*  sH = (float*)(smc + 131072);       // [k=128][m=8]  = 4 KiB
    const int tid = threadIdx.x;
    const int b0 = blockIdx.x * 8;

    for (int idx = tid; idx < 8192; idx += 256)
        ((int4*)sW)[idx] = ((const int4*)g_w1hh)[idx];
    for (int i = tid; i < 1024; i += 256) sH[i] = 0.f;
    __syncthreads();

    const int j = tid & 127, mh = tid >> 7;
    float cst[4] = {0.f, 0.f, 0.f, 0.f};
    const uint2* wp  = (const uint2*)sW + j;
    const float* hp0 = sH + mh * 4;

    for (int t = 0; t < 512; t++){
        size_t base = ((size_t)t * 1024 + b0) * 512 + (size_t)j * 4;
        float4 xv[2][2];
        #pragma unroll
        for (int p = 0; p < 2; p++){
            #pragma unroll
            for (int L = 0; L < 2; L++){
                int m = mh * 4 + p * 2 + L;
                ull raw = *(const ull*)(g_xw1h + base + (size_t)m * 512);
                const __half2* hp = (const __half2*)&raw;
                float2 f01 = __half22float2(hp[0]);
                float2 f23 = __half22float2(hp[1]);
                xv[p][L] = make_float4(f01.x, f01.y, f23.x, f23.y);
            }
        }

        ull acc[4][2] = {{0ull,0ull},{0ull,0ull},{0ull,0ull},{0ull,0ull}};
        #pragma unroll 4
        for (int k = 0; k < 128; k++){
            uint2 wraw = wp[k * 128];
            float2 w01 = __half22float2(*(const __half2*)&wraw.x);
            float2 w23 = __half22float2(*(const __half2*)&wraw.y);
            ulonglong2 hv = *(const ulonglong2*)(hp0 + k * 8);
            ull W0 = pack2(w01.x, w01.x);
            ull W1 = pack2(w01.y, w01.y);
            ull W2 = pack2(w23.x, w23.x);
            ull W3 = pack2(w23.y, w23.y);
            acc[0][0]=ffma2(W0,hv.x,acc[0][0]); acc[0][1]=ffma2(W0,hv.y,acc[0][1]);
            acc[1][0]=ffma2(W1,hv.x,acc[1][0]); acc[1][1]=ffma2(W1,hv.y,acc[1][1]);
            acc[2][0]=ffma2(W2,hv.x,acc[2][0]); acc[2][1]=ffma2(W2,hv.y,acc[2][1]);
            acc[3][0]=ffma2(W3,hv.x,acc[3][0]); acc[3][1]=ffma2(W3,hv.y,acc[3][1]);
        }
        __syncthreads();

        #pragma unroll
        for (int p = 0; p < 2; p++){
            float2 gi_ = unpack2(acc[0][p]);
            float2 gf_ = unpack2(acc[1][p]);
            float2 gg_ = unpack2(acc[2][p]);
            float2 go_ = unpack2(acc[3][p]);
            #pragma unroll
            for (int L = 0; L < 2; L++){
                const float4 x4 = xv[p][L];
                float ai = (L ? gi_.y : gi_.x) + x4.x;
                float af = (L ? gf_.y : gf_.x) + x4.y;
                float ag = (L ? gg_.y : gg_.x) + x4.z;
                float ao = (L ? go_.y : go_.x) + x4.w;
                float iv = sigf(ai), fv = sigf(af), gv = tanh_f(ag), ov = sigf(ao);
                int ci = p * 2 + L;
                float cn = fv * cst[ci] + iv * gv;
                cst[ci] = cn;
                float h = ov * tanh_f(cn);
                int m = mh * 4 + p * 2 + L;
                sH[j * 8 + m] = h;
                g_hs1[((size_t)t * 1024 + (b0 + m)) * 128 + j] = __float2half(h);
            }
        }
        __syncthreads();
    }
}

// =====================================================================
// REC2 (scalar FFMA2, proven) + fused FC head. 128 CTAs x 8 rows.
// =====================================================================
__global__ void __launch_bounds__(256) rec2_kernel(
    const float* __restrict__ fc1w, const float* __restrict__ fc1b,
    const float* __restrict__ fc2w, const float* __restrict__ fc2b,
    float* __restrict__ out)
{
    extern __shared__ char smc[];
    __half* sW = (__half*)smc;                 // [64][64][4] = 32 KiB
    float*  sH = (float*)(smc + 32768);        // [k=64][m=8] = 2 KiB
    const int tid = threadIdx.x;
    const int b0 = blockIdx.x * 8;

    for (int idx = tid; idx < 2048; idx += 256)
        ((int4*)sW)[idx] = ((const int4*)g_w2hh)[idx];
    for (int i = tid; i < 512; i += 256) sH[i] = 0.f;
    __syncthreads();

    const int j = tid & 63, ph = tid >> 6;
    const int m0 = ph * 2;
    float cst[2] = {0.f, 0.f};
    const uint2* wp  = (const uint2*)sW + j;
    const float* hp0 = sH + m0;

    for (int t = 0; t < 512; t++){
        size_t base = ((size_t)t * 1024 + b0) * 256 + (size_t)j * 4;
        float4 xv0, xv1;
        {
            ull raw0 = *(const ull*)(g_xw2h + base + (size_t)m0 * 256);
            ull raw1 = *(const ull*)(g_xw2h + base + (size_t)(m0 + 1) * 256);
            const __half2* h0 = (const __half2*)&raw0;
            const __half2* h1 = (const __half2*)&raw1;
            float2 a01 = __half22float2(h0[0]), a23 = __half22float2(h0[1]);
            float2 b01 = __half22float2(h1[0]), b23 = __half22float2(h1[1]);
            xv0 = make_float4(a01.x, a01.y, a23.x, a23.y);
            xv1 = make_float4(b01.x, b01.y, b23.x, b23.y);
        }

        ull acc[4] = {0ull, 0ull, 0ull, 0ull};
        #pragma unroll 4
        for (int k = 0; k < 64; k++){
            uint2 wraw = wp[k * 64];
            float2 w01 = __half22float2(*(const __half2*)&wraw.x);
            float2 w23 = __half22float2(*(const __half2*)&wraw.y);
            ull hv = *(const ull*)(hp0 + k * 8);
            acc[0] = ffma2(pack2(w01.x, w01.x), hv, acc[0]);
            acc[1] = ffma2(pack2(w01.y, w01.y), hv, acc[1]);
            acc[2] = ffma2(pack2(w23.x, w23.x), hv, acc[2]);
            acc[3] = ffma2(pack2(w23.y, w23.y), hv, acc[3]);
        }
        __syncthreads();

        float2 gi_ = unpack2(acc[0]);
        float2 gf_ = unpack2(acc[1]);
        float2 gg_ = unpack2(acc[2]);
        float2 go_ = unpack2(acc[3]);
        #pragma unroll
        for (int L = 0; L < 2; L++){
            const float4 x4 = L ? xv1 : xv0;
            float ai = (L ? gi_.y : gi_.x) + x4.x;
            float af = (L ? gf_.y : gf_.x) + x4.y;
            float ag = (L ? gg_.y : gg_.x) + x4.z;
            float ao = (L ? go_.y : go_.x) + x4.w;
            float iv = sigf(ai), fv = sigf(af), gv = tanh_f(ag), ov = sigf(ao);
            float cn = fv * cst[L] + iv * gv;
            cst[L] = cn;
            sH[j * 8 + m0 + L] = ov * tanh_f(cn);
        }
        __syncthreads();
    }

    const int m = tid >> 5, r = tid & 31;
    float s = fc1b[r];
    #pragma unroll 8
    for (int k = 0; k < 64; k++)
        s += sH[k * 8 + m] * fc1w[r * 64 + k];
    float z = fmaxf(s, 0.f) * fc2w[r];
    #pragma unroll
    for (int off = 16; off > 0; off >>= 1)
        z += __shfl_xor_sync(0xffffffffu, z, off);
    if (r == 0) out[b0 + m] = sigf(z + fc2b[0]);
}

// =====================================================================
extern "C" void kernel_launch(void* const* d_in, const int* in_sizes, int n_in,
                              void* d_out, int out_size)
{
    const float* X     = (const float*)d_in[0];
    const float* W1_ih = (const float*)d_in[1];
    const float* W1_hh = (const float*)d_in[2];
    const float* b1_ih = (const float*)d_in[3];
    const float* b1_hh = (const float*)d_in[4];
    const float* W2_ih = (const float*)d_in[5];
    const float* W2_hh = (const float*)d_in[6];
    const float* b2_ih = (const float*)d_in[7];
    const float* b2_hh = (const float*)d_in[8];
    const float* fc1w  = (const float*)d_in[9];
    const float* fc1b  = (const float*)d_in[10];
    const float* fc2w  = (const float*)d_in[11];
    const float* fc2b  = (const float*)d_in[12];
    float* out = (float*)d_out;

    const int g1_smem = 2 * 128 * 120 * 2;            // 61440 B
    const int g2_smem = 2 * 128 * 136 * 2;            // 69632 B
    const int r1_smem = 131072 + 4096;                // 135168 B
    const int r2_smem = 32768 + 2048;                 // 34816 B

    cudaFuncSetAttribute(gemm1_tc,    cudaFuncAttributeMaxDynamicSharedMemorySize, g1_smem);
    cudaFuncSetAttribute(gemm2_tc,    cudaFuncAttributeMaxDynamicSharedMemorySize, g2_smem);
    cudaFuncSetAttribute(rec1_kernel, cudaFuncAttributeMaxDynamicSharedMemorySize, r1_smem);
    cudaFuncSetAttribute(rec2_kernel, cudaFuncAttributeMaxDynamicSharedMemorySize, r2_smem);

    prep_kernel<<<128, 256>>>(W1_ih, W1_hh, b1_ih, b1_hh, W2_ih, W2_hh, b2_ih, b2_hh);
    gemm1_tc<<<dim3(4, 4096), 256, g1_smem>>>(X);
    rec1_kernel<<<128, 256, r1_smem>>>();
    gemm2_tc<<<dim3(2, 4096), 256, g2_smem>>>();
    rec2_kernel<<<128, 256, r2_smem>>>(fc1w, fc1b, fc2w, fc2b, out);
}

// round 7
// speedup vs baseline: 4.7582x; 2.5941x over previous
#include <cuda_runtime.h>
#include <cuda_fp16.h>
#include <cstdint>

typedef unsigned long long ull;

// ---------------- scratch (static device allocations; no cudaMalloc) ----------------
__device__ __half g_xw1h[268435456];  // [T=512][B=1024][n=512] fp16, n = j*4+q  (512 MiB)
__device__ __half g_xw2h[134217728];  // [T=512][B=1024][n=256] fp16, n = j*4+q  (256 MiB)
__device__ __half g_hs1[67108864];    // [T=512][B=1024][128]   fp16             (128 MiB)

// preconverted weights (fp16) + combined biases (fp32)
__device__ __half g_w1[512 * 112];    // W1_ih n-major: [n][k], k padded 100->112
__device__ __half g_w2[256 * 128];    // W2_ih n-major: [n][k=128]
__device__ __half g_w1hh[65536];      // W1_hh n-major: [n=512][k=128]
__device__ __half g_w2hh[16384];      // W2_hh n-major: [n=256][k=64]
__device__ float  g_b1[512];          // b1_ih+b1_hh at n = j*4+q
__device__ float  g_b2[256];          // b2_ih+b2_hh at n = j*4+q

// ---------------- helpers ----------------
__device__ __forceinline__ float sigf(float x){ return 1.f / (1.f + __expf(-x)); }
__device__ __forceinline__ float tanha(float x){
    float y; asm("tanh.approx.f32 %0, %1;" : "=f"(y) : "f"(x)); return y;
}
__device__ __forceinline__ float siga(float x){ return fmaf(0.5f, tanha(0.5f * x), 0.5f); }

__device__ __forceinline__ uint32_t smem_u32(const void* p){
    return (uint32_t)__cvta_generic_to_shared(p);
}

__device__ __forceinline__ void mma16816(float& c0, float& c1, float& c2, float& c3,
                                         uint32_t a0, uint32_t a1, uint32_t a2, uint32_t a3,
                                         uint32_t b0, uint32_t b1){
    asm("mma.sync.aligned.m16n8k16.row.col.f32.f16.f16.f32 "
        "{%0,%1,%2,%3}, {%4,%5,%6,%7}, {%8,%9}, {%0,%1,%2,%3};"
        : "+f"(c0), "+f"(c1), "+f"(c2), "+f"(c3)
        : "r"(a0), "r"(a1), "r"(a2), "r"(a3), "r"(b0), "r"(b1));
}

__device__ __forceinline__ void ldsm_x4(uint32_t& r0, uint32_t& r1, uint32_t& r2, uint32_t& r3,
                                        uint32_t addr){
    asm("ldmatrix.sync.aligned.m8n8.x4.shared.b16 {%0,%1,%2,%3}, [%4];"
        : "=r"(r0), "=r"(r1), "=r"(r2), "=r"(r3) : "r"(addr));
}

// =====================================================================
// PREP: one-shot weight conversion
// =====================================================================
__global__ void __launch_bounds__(256) prep_kernel(
    const float* __restrict__ W1_ih, const float* __restrict__ W1_hh,
    const float* __restrict__ b1_ih, const float* __restrict__ b1_hh,
    const float* __restrict__ W2_ih, const float* __restrict__ W2_hh,
    const float* __restrict__ b2_ih, const float* __restrict__ b2_hh)
{
    const int tid = blockIdx.x * blockDim.x + threadIdx.x;
    const int stride = gridDim.x * blockDim.x;
    for (int i = tid; i < 512 * 112; i += stride){
        int n = i / 112, k = i - n * 112;
        int j = n >> 2, q = n & 3;
        g_w1[i] = __float2half(k < 100 ? W1_ih[(q * 128 + j) * 100 + k] : 0.f);
    }
    for (int i = tid; i < 256 * 128; i += stride){
        int n = i >> 7, k = i & 127;
        int j = n >> 2, q = n & 3;
        g_w2[i] = __float2half(W2_ih[(q * 64 + j) * 128 + k]);
    }
    for (int i = tid; i < 65536; i += stride){
        int n = i >> 7, k = i & 127;
        int j = n >> 2, q = n & 3;
        g_w1hh[i] = __float2half(W1_hh[(q * 128 + j) * 128 + k]);
    }
    for (int i = tid; i < 16384; i += stride){
        int n = i >> 6, k = i & 63;
        int j = n >> 2, q = n & 3;
        g_w2hh[i] = __float2half(W2_hh[(q * 64 + j) * 64 + k]);
    }
    for (int i = tid; i < 512; i += stride){
        int j = i >> 2, q = i & 3;
        g_b1[i] = b1_ih[q * 128 + j] + b1_hh[q * 128 + j];
    }
    for (int i = tid; i < 256; i += stride){
        int j = i >> 2, q = i & 3;
        g_b2[i] = b2_ih[q * 64 + j] + b2_hh[q * 64 + j];
    }
}

// =====================================================================
// GEMM1 (tensor core, unchanged from R4)
// =====================================================================
__global__ void __launch_bounds__(256) gemm1_tc(const float* __restrict__ X)
{
    extern __shared__ __half sm[];
    __half* sA = sm;               // [128][120]
    __half* sB = sm + 128 * 120;   // [128][120] n-major
    const int tid = threadIdx.x;
    const int cb = blockIdx.x;
    const int rb = blockIdx.y;
    const int r0 = rb * 128;
    const int n0c = cb * 128;

    const float4* X4 = (const float4*)(X + (size_t)r0 * 100);
    for (int idx = tid; idx < 3200; idx += 256){
        int row = idx / 25, c4 = idx - row * 25;
        float4 v = X4[row * 25 + c4];
        __half2 h0 = __floats2half2_rn(v.x, v.y);
        __half2 h1 = __floats2half2_rn(v.z, v.w);
        ull packed = ((ull)(*(uint32_t*)&h1) << 32) | (*(uint32_t*)&h0);
        *(ull*)(sA + row * 120 + c4 * 4) = packed;
    }
    for (int idx = tid; idx < 768; idx += 256){
        int row = idx / 6, e = (idx - row * 6) * 2;
        *(uint32_t*)(sA + row * 120 + 100 + e) = 0u;
    }
    for (int idx = tid; idx < 1792; idx += 256){
        int nn = idx / 14, c8 = (idx - nn * 14) * 8;
        *(int4*)(sB + nn * 120 + c8) = *(const int4*)(g_w1 + (size_t)(n0c + nn) * 112 + c8);
    }
    __syncthreads();

    const int w = tid >> 5, lane = tid & 31;
    const int wm = w >> 2, wn = w & 3;
    const int m0w = wm * 64, n0w = wn * 32;
    const int gp = lane >> 2, tig = lane & 3;

    float acc[4][4][4];
    #pragma unroll
    for (int mt = 0; mt < 4; mt++)
        #pragma unroll
        for (int nt = 0; nt < 4; nt++){
            acc[mt][nt][0]=0.f; acc[mt][nt][1]=0.f; acc[mt][nt][2]=0.f; acc[mt][nt][3]=0.f;
        }

    float2 bias[4];
    #pragma unroll
    for (int nt = 0; nt < 4; nt++)
        bias[nt] = *(const float2*)(g_b1 + n0c + n0w + nt * 8 + 2 * tig);

    #pragma unroll
    for (int kt = 0; kt < 7; kt++){
        const int k0 = kt * 16;
        uint32_t af[4][4];
        #pragma unroll
        for (int mt = 0; mt < 4; mt++){
            const __half* ap = sA + (m0w + mt * 16 + gp) * 120 + k0 + 2 * tig;
            af[mt][0] = *(const uint32_t*)ap;
            af[mt][1] = *(const uint32_t*)(ap + 8 * 120);
            af[mt][2] = *(const uint32_t*)(ap + 8);
            af[mt][3] = *(const uint32_t*)(ap + 8 * 120 + 8);
        }
        #pragma unroll
        for (int nt = 0; nt < 4; nt++){
            const __half* bp = sB + (n0w + nt * 8 + gp) * 120 + k0 + 2 * tig;
            uint32_t b0 = *(const uint32_t*)bp;
            uint32_t b1 = *(const uint32_t*)(bp + 8);
            #pragma unroll
            for (int mt = 0; mt < 4; mt++)
                mma16816(acc[mt][nt][0], acc[mt][nt][1], acc[mt][nt][2], acc[mt][nt][3],
                         af[mt][0], af[mt][1], af[mt][2], af[mt][3], b0, b1);
        }
    }

    __syncthreads();
    __half* stg = sm;   // [128][136]
    #pragma unroll
    for (int mt = 0; mt < 4; mt++){
        int ra = m0w + mt * 16 + gp;
        #pragma unroll
        for (int nt = 0; nt < 4; nt++){
            int nl = n0w + nt * 8 + 2 * tig;
            __half2 v0 = __floats2half2_rn(acc[mt][nt][0] + bias[nt].x, acc[mt][nt][1] + bias[nt].y);
            __half2 v1 = __floats2half2_rn(acc[mt][nt][2] + bias[nt].x, acc[mt][nt][3] + bias[nt].y);
            *(__half2*)(stg + ra * 136 + nl) = v0;
            *(__half2*)(stg + (ra + 8) * 136 + nl) = v1;
        }
    }
    __syncthreads();
    #pragma unroll
    for (int i = 0; i < 8; i++){
        int idx = tid + i * 256;
        int row = idx >> 4, col8 = (idx & 15) * 8;
        int r = r0 + row;
        size_t orow = (size_t)(r & 511) * 1024 + (r >> 9);
        *(int4*)(g_xw1h + orow * 512 + n0c + col8) = *(const int4*)(stg + row * 136 + col8);
    }
}

// =====================================================================
// GEMM2 (tensor core, unchanged from R4)
// =====================================================================
__global__ void __launch_bounds__(256) gemm2_tc()
{
    extern __shared__ __half sm[];
    __half* sA = sm;               // [128][136]
    __half* sB = sm + 128 * 136;   // [128][136]
    const int tid = threadIdx.x;
    const int cb = blockIdx.x;
    const int rb = blockIdx.y;
    const int r0 = rb * 128;
    const int n0c = cb * 128;

    for (int idx = tid; idx < 2048; idx += 256){
        int row = idx >> 4, c8 = (idx & 15) * 8;
        *(int4*)(sA + row * 136 + c8) = *(const int4*)(g_hs1 + (size_t)(r0 + row) * 128 + c8);
    }
    for (int idx = tid; idx < 2048; idx += 256){
        int nn = idx >> 4, c8 = (idx & 15) * 8;
        *(int4*)(sB + nn * 136 + c8) = *(const int4*)(g_w2 + (size_t)(n0c + nn) * 128 + c8);
    }
    __syncthreads();

    const int w = tid >> 5, lane = tid & 31;
    const int wm = w >> 2, wn = w & 3;
    const int m0w = wm * 64, n0w = wn * 32;
    const int gp = lane >> 2, tig = lane & 3;

    float acc[4][4][4];
    #pragma unroll
    for (int mt = 0; mt < 4; mt++)
        #pragma unroll
        for (int nt = 0; nt < 4; nt++){
            acc[mt][nt][0]=0.f; acc[mt][nt][1]=0.f; acc[mt][nt][2]=0.f; acc[mt][nt][3]=0.f;
        }

    float2 bias[4];
    #pragma unroll
    for (int nt = 0; nt < 4; nt++)
        bias[nt] = *(const float2*)(g_b2 + n0c + n0w + nt * 8 + 2 * tig);

    #pragma unroll
    for (int kt = 0; kt < 8; kt++){
        const int k0 = kt * 16;
        uint32_t af[4][4];
        #pragma unroll
        for (int mt = 0; mt < 4; mt++){
            const __half* ap = sA + (m0w + mt * 16 + gp) * 136 + k0 + 2 * tig;
            af[mt][0] = *(const uint32_t*)ap;
            af[mt][1] = *(const uint32_t*)(ap + 8 * 136);
            af[mt][2] = *(const uint32_t*)(ap + 8);
            af[mt][3] = *(const uint32_t*)(ap + 8 * 136 + 8);
        }
        #pragma unroll
        for (int nt = 0; nt < 4; nt++){
            const __half* bp = sB + (n0w + nt * 8 + gp) * 136 + k0 + 2 * tig;
            uint32_t b0 = *(const uint32_t*)bp;
            uint32_t b1 = *(const uint32_t*)(bp + 8);
            #pragma unroll
            for (int mt = 0; mt < 4; mt++)
                mma16816(acc[mt][nt][0], acc[mt][nt][1], acc[mt][nt][2], acc[mt][nt][3],
                         af[mt][0], af[mt][1], af[mt][2], af[mt][3], b0, b1);
        }
    }

    __syncthreads();
    __half* stg = sm;
    #pragma unroll
    for (int mt = 0; mt < 4; mt++){
        int ra = m0w + mt * 16 + gp;
        #pragma unroll
        for (int nt = 0; nt < 4; nt++){
            int nl = n0w + nt * 8 + 2 * tig;
            __half2 v0 = __floats2half2_rn(acc[mt][nt][0] + bias[nt].x, acc[mt][nt][1] + bias[nt].y);
            __half2 v1 = __floats2half2_rn(acc[mt][nt][2] + bias[nt].x, acc[mt][nt][3] + bias[nt].y);
            *(__half2*)(stg + ra * 136 + nl) = v0;
            *(__half2*)(stg + (ra + 8) * 136 + nl) = v1;
        }
    }
    __syncthreads();
    #pragma unroll
    for (int i = 0; i < 8; i++){
        int idx = tid + i * 256;
        int row = idx >> 4, col8 = (idx & 15) * 8;
        *(int4*)(g_xw2h + (size_t)(r0 + row) * 256 + n0c + col8) = *(const int4*)(stg + row * 136 + col8);
    }
}

// =====================================================================
// REC1 (tensor core v2): 128 CTAs x 8 batch rows, 8 warps.
// W1_hh in SMEM n-major; B-frags via ldmatrix.x4 each step; A rows 8-15 = 0.
// =====================================================================
__global__ void __launch_bounds__(256, 1) rec1_kernel()
{
    extern __shared__ __half smr[];
    __half* sB = smr;                  // [512][136]  weights, n-major
    __half* sH = smr + 512 * 136;      // [2][8][136] h double buffer
    const int tid  = threadIdx.x;
    const int w    = tid >> 5;
    const int lane = tid & 31;
    const int gp   = lane >> 2;
    const int tig  = lane & 3;
    const bool odd = lane & 1;
    const int b0   = blockIdx.x * 8;

    for (int idx = tid; idx < 8192; idx += 256){
        int nn = idx >> 4, c8 = (idx & 15) * 8;
        *(int4*)(sB + nn * 136 + c8) = *(const int4*)(g_w1hh + nn * 128 + c8);
    }
    for (int i = tid; i < 1088; i += 256) ((uint32_t*)sH)[i] = 0u;
    __syncthreads();

    // ldmatrix base addresses: ntp in 0..3 covers ntiles 2ntp, 2ntp+1
    uint32_t bb[4];
    {
        int rowo = (lane & 7) + ((lane & 16) ? 8 : 0);
        int kcol = ((lane >> 3) & 1) * 8;
        uint32_t base = smem_u32(sB);
        #pragma unroll
        for (int ntp = 0; ntp < 4; ntp++)
            bb[ntp] = base + (uint32_t)(((w * 64 + ntp * 16 + rowo) * 136 + kcol) * 2);
    }

    float cst[8];
    #pragma unroll
    for (int nt = 0; nt < 8; nt++) cst[nt] = 0.f;

    const uint32_t zero = 0u;
    const int cA = w * 64 + 2 * tig;

    for (int t = 0; t < 512; t++){
        const __half* hr = sH + (1 - (t & 1)) * 8 * 136;
        __half*       hw = sH + (t & 1) * 8 * 136;

        // prefetch xw (consumed in epilogue)
        uint32_t xh[8];
        {
            const __half* xbase = g_xw1h + ((size_t)t * 1024 + b0 + gp) * 512 + cA;
            #pragma unroll
            for (int nt = 0; nt < 8; nt++)
                xh[nt] = *(const uint32_t*)(xbase + nt * 8);
        }

        float acc[8][4];
        #pragma unroll
        for (int nt = 0; nt < 8; nt++){
            acc[nt][0]=0.f; acc[nt][1]=0.f; acc[nt][2]=0.f; acc[nt][3]=0.f;
        }

        #pragma unroll
        for (int kt = 0; kt < 8; kt++){
            const int k0 = kt * 16;
            const __half* ap = hr + gp * 136 + k0 + 2 * tig;
            uint32_t a0 = *(const uint32_t*)ap;
            uint32_t a2 = *(const uint32_t*)(ap + 8);
            #pragma unroll
            for (int ntp = 0; ntp < 4; ntp++){
                uint32_t r0, r1, r2, r3;
                ldsm_x4(r0, r1, r2, r3, bb[ntp] + (uint32_t)(k0 * 2));
                mma16816(acc[2*ntp][0],   acc[2*ntp][1],   acc[2*ntp][2],   acc[2*ntp][3],
                         a0, zero, a2, zero, r0, r1);
                mma16816(acc[2*ntp+1][0], acc[2*ntp+1][1], acc[2*ntp+1][2], acc[2*ntp+1][3],
                         a0, zero, a2, zero, r2, r3);
            }
        }

        #pragma unroll
        for (int nt = 0; nt < 8; nt++){
            float2 x = __half22float2(*(const __half2*)&xh[nt]);
            float p0 = acc[nt][0] + x.x;
            float p1 = acc[nt][1] + x.y;
            float q0 = __shfl_xor_sync(0xffffffffu, p0, 1);
            float q1 = __shfl_xor_sync(0xffffffffu, p1, 1);
            float gi = odd ? q0 : p0;
            float gf = odd ? q1 : p1;
            float gg = odd ? p0 : q0;
            float go = odd ? p1 : q1;
            float c = siga(gf) * cst[nt] + siga(gi) * tanha(gg);
            cst[nt] = c;
            float h = siga(go) * tanha(c);
            if (!odd)
                hw[gp * 136 + (w * 16 + nt * 2 + (tig >> 1))] = __float2half(h);
        }
        __syncthreads();

        // coalesced copy h_t (8 x 128) -> g_hs1
        if (tid < 128){
            int row = tid >> 4, c8 = (tid & 15) * 8;
            *(int4*)(g_hs1 + ((size_t)t * 1024 + b0 + row) * 128 + c8) =
                *(const int4*)(hw + row * 136 + c8);
        }
    }
}

// =====================================================================
// REC2 (tensor core v2) + fused FC head. 128 CTAs x 8 rows, 8 warps.
// =====================================================================
__global__ void __launch_bounds__(256, 1) rec2_kernel(
    const float* __restrict__ fc1w, const float* __restrict__ fc1b,
    const float* __restrict__ fc2w, const float* __restrict__ fc2b,
    float* __restrict__ out)
{
    __shared__ __half sB[256 * 72];    // weights n-major
    __shared__ __half sH[2 * 8 * 72];  // h double buffer
    const int tid  = threadIdx.x;
    const int w    = tid >> 5;
    const int lane = tid & 31;
    const int gp   = lane >> 2;
    const int tig  = lane & 3;
    const bool odd = lane & 1;
    const int b0   = blockIdx.x * 8;

    for (int idx = tid; idx < 2048; idx += 256){
        int nn = idx >> 3, c8 = (idx & 7) * 8;
        *(int4*)(sB + nn * 72 + c8) = *(const int4*)(g_w2hh + nn * 64 + c8);
    }
    for (int i = tid; i < 576; i += 256) ((uint32_t*)sH)[i] = 0u;
    __syncthreads();

    uint32_t bb[2];
    {
        int rowo = (lane & 7) + ((lane & 16) ? 8 : 0);
        int kcol = ((lane >> 3) & 1) * 8;
        uint32_t base = smem_u32(sB);
        #pragma unroll
        for (int ntp = 0; ntp < 2; ntp++)
            bb[ntp] = base + (uint32_t)(((w * 32 + ntp * 16 + rowo) * 72 + kcol) * 2);
    }

    float cst[4] = {0.f, 0.f, 0.f, 0.f};
    const uint32_t zero = 0u;
    const int cA = w * 32 + 2 * tig;

    for (int t = 0; t < 512; t++){
        const __half* hr = sH + (1 - (t & 1)) * 8 * 72;
        __half*       hw = sH + (t & 1) * 8 * 72;

        uint32_t xh[4];
        {
            const __half* xbase = g_xw2h + ((size_t)t * 1024 + b0 + gp) * 256 + cA;
            #pragma unroll
            for (int nt = 0; nt < 4; nt++)
                xh[nt] = *(const uint32_t*)(xbase + nt * 8);
        }

        float acc[4][4];
        #pragma unroll
        for (int nt = 0; nt < 4; nt++){
            acc[nt][0]=0.f; acc[nt][1]=0.f; acc[nt][2]=0.f; acc[nt][3]=0.f;
        }

        #pragma unroll
        for (int kt = 0; kt < 4; kt++){
            const int k0 = kt * 16;
            const __half* ap = hr + gp * 72 + k0 + 2 * tig;
            uint32_t a0 = *(const uint32_t*)ap;
            uint32_t a2 = *(const uint32_t*)(ap + 8);
            #pragma unroll
            for (int ntp = 0; ntp < 2; ntp++){
                uint32_t r0, r1, r2, r3;
                ldsm_x4(r0, r1, r2, r3, bb[ntp] + (uint32_t)(k0 * 2));
                mma16816(acc[2*ntp][0],   acc[2*ntp][1],   acc[2*ntp][2],   acc[2*ntp][3],
                         a0, zero, a2, zero, r0, r1);
                mma16816(acc[2*ntp+1][0], acc[2*ntp+1][1], acc[2*ntp+1][2], acc[2*ntp+1][3],
                         a0, zero, a2, zero, r2, r3);
            }
        }

        #pragma unroll
        for (int nt = 0; nt < 4; nt++){
            float2 x = __half22float2(*(const __half2*)&xh[nt]);
            float p0 = acc[nt][0] + x.x;
            float p1 = acc[nt][1] + x.y;
            float q0 = __shfl_xor_sync(0xffffffffu, p0, 1);
            float q1 = __shfl_xor_sync(0xffffffffu, p1, 1);
            float gi = odd ? q0 : p0;
            float gf = odd ? q1 : p1;
            float gg = odd ? p0 : q0;
            float go = odd ? p1 : q1;
            float c = siga(gf) * cst[nt] + siga(gi) * tanha(gg);
            cst[nt] = c;
            float h = siga(go) * tanha(c);
            if (!odd)
                hw[gp * 72 + (w * 8 + nt * 2 + (tig >> 1))] = __float2half(h);
        }
        __syncthreads();
    }

    // ---- fused FC head: final h2 in buf 1 (t=511 wrote sH + 8*72) ----
    const __half* hf = sH + 8 * 72;
    const int m = w;            // 8 warps -> batch rows b0..b0+7
    const int r = lane;
    float s = (r < 32) ? fc1b[r] : 0.f;
    #pragma unroll 8
    for (int k = 0; k < 64; k++)
        s += __half2float(hf[m * 72 + k]) * fc1w[r * 64 + k];
    float z = fmaxf(s, 0.f) * fc2w[r];
    #pragma unroll
    for (int off = 16; off > 0; off >>= 1)
        z += __shfl_xor_sync(0xffffffffu, z, off);
    if (r == 0) out[b0 + m] = sigf(z + fc2b[0]);
}

// =====================================================================
extern "C" void kernel_launch(void* const* d_in, const int* in_sizes, int n_in,
                              void* d_out, int out_size)
{
    const float* X     = (const float*)d_in[0];
    const float* W1_ih = (const float*)d_in[1];
    const float* W1_hh = (const float*)d_in[2];
    const float* b1_ih = (const float*)d_in[3];
    const float* b1_hh = (const float*)d_in[4];
    const float* W2_ih = (const float*)d_in[5];
    const float* W2_hh = (const float*)d_in[6];
    const float* b2_ih = (const float*)d_in[7];
    const float* b2_hh = (const float*)d_in[8];
    const float* fc1w  = (const float*)d_in[9];
    const float* fc1b  = (const float*)d_in[10];
    const float* fc2w  = (const float*)d_in[11];
    const float* fc2b  = (const float*)d_in[12];
    float* out = (float*)d_out;

    const int g1_smem = 2 * 128 * 120 * 2;            // 61440 B
    const int g2_smem = 2 * 128 * 136 * 2;            // 69632 B
    const int r1_smem = (512 * 136 + 2 * 8 * 136) * 2; // 143616 B

    cudaFuncSetAttribute(gemm1_tc,    cudaFuncAttributeMaxDynamicSharedMemorySize, g1_smem);
    cudaFuncSetAttribute(gemm2_tc,    cudaFuncAttributeMaxDynamicSharedMemorySize, g2_smem);
    cudaFuncSetAttribute(rec1_kernel, cudaFuncAttributeMaxDynamicSharedMemorySize, r1_smem);

    prep_kernel<<<128, 256>>>(W1_ih, W1_hh, b1_ih, b1_hh, W2_ih, W2_hh, b2_ih, b2_hh);
    gemm1_tc<<<dim3(4, 4096), 256, g1_smem>>>(X);
    rec1_kernel<<<128, 256, r1_smem>>>();
    gemm2_tc<<<dim3(2, 4096), 256, g2_smem>>>();
    rec2_kernel<<<128, 256>>>(fc1w, fc1b, fc2w, fc2b, out);
}

// round 9
// speedup vs baseline: 5.0384x; 1.0589x over previous
#include <cuda_runtime.h>
#include <cuda_fp16.h>
#include <cstdint>

typedef unsigned long long ull;

// ---------------- scratch (static device allocations; no cudaMalloc) ----------------
__device__ __half g_xw1h[268435456];  // [T=512][B=1024][n=512] fp16  (512 MiB)
__device__ __half g_xw2h[134217728];  // [T=512][B=1024][n=256] fp16  (256 MiB)
__device__ __half g_hs1[67108864];    // [T=512][B=1024][128]   fp16  (128 MiB)

// preconverted weights (fp16) + combined biases (fp32)
// Gate-column mapping (layer 1): n = wq*64 + s, wq=j/16;
//   s = 2*(j%16) + q            for q in {0,1}  (i,f pairs, tiles 0..3 of warp)
//   s = 32 + 2*(j%16) + (q-2)   for q in {2,3}  (g,o pairs, tiles 4..7)
// Layer 2 analogous with 8 units/warp and 32 cols/warp.
__device__ __half g_w1[512 * 112];    // W1_ih n-major: [n][k], k padded 100->112
__device__ __half g_w2[256 * 128];    // W2_ih n-major: [n][k=128]
__device__ __half g_w1hh[65536];      // W1_hh n-major: [n=512][k=128]
__device__ __half g_w2hh[16384];      // W2_hh n-major: [n=256][k=64]
__device__ float  g_b1[512];
__device__ float  g_b2[256];

// ---------------- helpers ----------------
__device__ __forceinline__ float sigf(float x){ return 1.f / (1.f + __expf(-x)); }
__device__ __forceinline__ float tanha(float x){
    float y; asm("tanh.approx.f32 %0, %1;" : "=f"(y) : "f"(x)); return y;
}
__device__ __forceinline__ float siga(float x){ return fmaf(0.5f, tanha(0.5f * x), 0.5f); }

__device__ __forceinline__ uint32_t smem_u32(const void* p){
    return (uint32_t)__cvta_generic_to_shared(p);
}

__device__ __forceinline__ void mma16816(float& c0, float& c1, float& c2, float& c3,
                                         uint32_t a0, uint32_t a1, uint32_t a2, uint32_t a3,
                                         uint32_t b0, uint32_t b1){
    asm("mma.sync.aligned.m16n8k16.row.col.f32.f16.f16.f32 "
        "{%0,%1,%2,%3}, {%4,%5,%6,%7}, {%8,%9}, {%0,%1,%2,%3};"
        : "+f"(c0), "+f"(c1), "+f"(c2), "+f"(c3)
        : "r"(a0), "r"(a1), "r"(a2), "r"(a3), "r"(b0), "r"(b1));
}

__device__ __forceinline__ void ldsm_x4(uint32_t& r0, uint32_t& r1, uint32_t& r2, uint32_t& r3,
                                        uint32_t addr){
    asm("ldmatrix.sync.aligned.m8n8.x4.shared.b16 {%0,%1,%2,%3}, [%4];"
        : "=r"(r0), "=r"(r1), "=r"(r2), "=r"(r3) : "r"(addr));
}

// gate mapping helpers (prep only)
__device__ __forceinline__ void n_to_gj1(int n, int& g, int& j){
    int wq = n >> 6, s = n & 63;
    int q;
    if (s < 32){ j = wq * 16 + (s >> 1); q = s & 1; }
    else        { int s2 = s - 32; j = wq * 16 + (s2 >> 1); q = 2 + (s2 & 1); }
    g = q * 128 + j;
}
__device__ __forceinline__ void n_to_gj2(int n, int& g, int& j){
    int wq = n >> 5, s = n & 31;
    int q;
    if (s < 16){ j = wq * 8 + (s >> 1); q = s & 1; }
    else        { int s2 = s - 16; j = wq * 8 + (s2 >> 1); q = 2 + (s2 & 1); }
    g = q * 64 + j;
}

// =====================================================================
// PREP: one-shot weight conversion with gate-pair column mapping
// =====================================================================
__global__ void __launch_bounds__(256) prep_kernel(
    const float* __restrict__ W1_ih, const float* __restrict__ W1_hh,
    const float* __restrict__ b1_ih, const float* __restrict__ b1_hh,
    const float* __restrict__ W2_ih, const float* __restrict__ W2_hh,
    const float* __restrict__ b2_ih, const float* __restrict__ b2_hh)
{
    const int tid = blockIdx.x * blockDim.x + threadIdx.x;
    const int stride = gridDim.x * blockDim.x;
    for (int i = tid; i < 512 * 112; i += stride){
        int n = i / 112, k = i - n * 112;
        int g, j; n_to_gj1(n, g, j);
        g_w1[i] = __float2half(k < 100 ? W1_ih[g * 100 + k] : 0.f);
    }
    for (int i = tid; i < 256 * 128; i += stride){
        int n = i >> 7, k = i & 127;
        int g, j; n_to_gj2(n, g, j);
        g_w2[i] = __float2half(W2_ih[g * 128 + k]);
    }
    for (int i = tid; i < 65536; i += stride){
        int n = i >> 7, k = i & 127;
        int g, j; n_to_gj1(n, g, j);
        g_w1hh[i] = __float2half(W1_hh[g * 128 + k]);
    }
    for (int i = tid; i < 16384; i += stride){
        int n = i >> 6, k = i & 63;
        int g, j; n_to_gj2(n, g, j);
        g_w2hh[i] = __float2half(W2_hh[g * 64 + k]);
    }
    for (int i = tid; i < 512; i += stride){
        int g, j; n_to_gj1(i, g, j);
        g_b1[i] = b1_ih[g] + b1_hh[g];
    }
    for (int i = tid; i < 256; i += stride){
        int g, j; n_to_gj2(i, g, j);
        g_b2[i] = b2_ih[g] + b2_hh[g];
    }
}

// =====================================================================
// GEMM1 (tensor core)
// =====================================================================
__global__ void __launch_bounds__(256) gemm1_tc(const float* __restrict__ X)
{
    extern __shared__ __half sm[];
    __half* sA = sm;               // [128][120]
    __half* sB = sm + 128 * 120;   // [128][120] n-major
    const int tid = threadIdx.x;
    const int cb = blockIdx.x;
    const int rb = blockIdx.y;
    const int r0 = rb * 128;
    const int n0c = cb * 128;

    const float4* X4 = (const float4*)(X + (size_t)r0 * 100);
    for (int idx = tid; idx < 3200; idx += 256){
        int row = idx / 25, c4 = idx - row * 25;
        float4 v = X4[row * 25 + c4];
        __half2 h0 = __floats2half2_rn(v.x, v.y);
        __half2 h1 = __floats2half2_rn(v.z, v.w);
        ull packed = ((ull)(*(uint32_t*)&h1) << 32) | (*(uint32_t*)&h0);
        *(ull*)(sA + row * 120 + c4 * 4) = packed;
    }
    for (int idx = tid; idx < 768; idx += 256){
        int row = idx / 6, e = (idx - row * 6) * 2;
        *(uint32_t*)(sA + row * 120 + 100 + e) = 0u;
    }
    for (int idx = tid; idx < 1792; idx += 256){
        int nn = idx / 14, c8 = (idx - nn * 14) * 8;
        *(int4*)(sB + nn * 120 + c8) = *(const int4*)(g_w1 + (size_t)(n0c + nn) * 112 + c8);
    }
    __syncthreads();

    const int w = tid >> 5, lane = tid & 31;
    const int wm = w >> 2, wn = w & 3;
    const int m0w = wm * 64, n0w = wn * 32;
    const int gp = lane >> 2, tig = lane & 3;

    float acc[4][4][4];
    #pragma unroll
    for (int mt = 0; mt < 4; mt++)
        #pragma unroll
        for (int nt = 0; nt < 4; nt++){
            acc[mt][nt][0]=0.f; acc[mt][nt][1]=0.f; acc[mt][nt][2]=0.f; acc[mt][nt][3]=0.f;
        }

    float2 bias[4];
    #pragma unroll
    for (int nt = 0; nt < 4; nt++)
        bias[nt] = *(const float2*)(g_b1 + n0c + n0w + nt * 8 + 2 * tig);

    #pragma unroll
    for (int kt = 0; kt < 7; kt++){
        const int k0 = kt * 16;
        uint32_t af[4][4];
        #pragma unroll
        for (int mt = 0; mt < 4; mt++){
            const __half* ap = sA + (m0w + mt * 16 + gp) * 120 + k0 + 2 * tig;
            af[mt][0] = *(const uint32_t*)ap;
            af[mt][1] = *(const uint32_t*)(ap + 8 * 120);
            af[mt][2] = *(const uint32_t*)(ap + 8);
            af[mt][3] = *(const uint32_t*)(ap + 8 * 120 + 8);
        }
        #pragma unroll
        for (int nt = 0; nt < 4; nt++){
            const __half* bp = sB + (n0w + nt * 8 + gp) * 120 + k0 + 2 * tig;
            uint32_t b0 = *(const uint32_t*)bp;
            uint32_t b1 = *(const uint32_t*)(bp + 8);
            #pragma unroll
            for (int mt = 0; mt < 4; mt++)
                mma16816(acc[mt][nt][0], acc[mt][nt][1], acc[mt][nt][2], acc[mt][nt][3],
                         af[mt][0], af[mt][1], af[mt][2], af[mt][3], b0, b1);
        }
    }

    __syncthreads();
    __half* stg = sm;   // [128][136]
    #pragma unroll
    for (int mt = 0; mt < 4; mt++){
        int ra = m0w + mt * 16 + gp;
        #pragma unroll
        for (int nt = 0; nt < 4; nt++){
            int nl = n0w + nt * 8 + 2 * tig;
            __half2 v0 = __floats2half2_rn(acc[mt][nt][0] + bias[nt].x, acc[mt][nt][1] + bias[nt].y);
            __half2 v1 = __floats2half2_rn(acc[mt][nt][2] + bias[nt].x, acc[mt][nt][3] + bias[nt].y);
            *(__half2*)(stg + ra * 136 + nl) = v0;
            *(__half2*)(stg + (ra + 8) * 136 + nl) = v1;
        }
    }
    __syncthreads();
    #pragma unroll
    for (int i = 0; i < 8; i++){
        int idx = tid + i * 256;
        int row = idx >> 4, col8 = (idx & 15) * 8;
        int r = r0 + row;
        size_t orow = (size_t)(r & 511) * 1024 + (r >> 9);
        *(int4*)(g_xw1h + orow * 512 + n0c + col8) = *(const int4*)(stg + row * 136 + col8);
    }
}

// =====================================================================
// GEMM2 (tensor core)
// =====================================================================
__global__ void __launch_bounds__(256) gemm2_tc()
{
    extern __shared__ __half sm[];
    __half* sA = sm;               // [128][136]
    __half* sB = sm + 128 * 136;   // [128][136]
    const int tid = threadIdx.x;
    const int cb = blockIdx.x;
    const int rb = blockIdx.y;
    const int r0 = rb * 128;
    const int n0c = cb * 128;

    for (int idx = tid; idx < 2048; idx += 256){
        int row = idx >> 4, c8 = (idx & 15) * 8;
        *(int4*)(sA + row * 136 + c8) = *(const int4*)(g_hs1 + (size_t)(r0 + row) * 128 + c8);
    }
    for (int idx = tid; idx < 2048; idx += 256){
        int nn = idx >> 4, c8 = (idx & 15) * 8;
        *(int4*)(sB + nn * 136 + c8) = *(const int4*)(g_w2 + (size_t)(n0c + nn) * 128 + c8);
    }
    __syncthreads();

    const int w = tid >> 5, lane = tid & 31;
    const int wm = w >> 2, wn = w & 3;
    const int m0w = wm * 64, n0w = wn * 32;
    const int gp = lane >> 2, tig = lane & 3;

    float acc[4][4][4];
    #pragma unroll
    for (int mt = 0; mt < 4; mt++)
        #pragma unroll
        for (int nt = 0; nt < 4; nt++){
            acc[mt][nt][0]=0.f; acc[mt][nt][1]=0.f; acc[mt][nt][2]=0.f; acc[mt][nt][3]=0.f;
        }

    float2 bias[4];
    #pragma unroll
    for (int nt = 0; nt < 4; nt++)
        bias[nt] = *(const float2*)(g_b2 + n0c + n0w + nt * 8 + 2 * tig);

    #pragma unroll
    for (int kt = 0; kt < 8; kt++){
        const int k0 = kt * 16;
        uint32_t af[4][4];
        #pragma unroll
        for (int mt = 0; mt < 4; mt++){
            const __half* ap = sA + (m0w + mt * 16 + gp) * 136 + k0 + 2 * tig;
            af[mt][0] = *(const uint32_t*)ap;
            af[mt][1] = *(const uint32_t*)(ap + 8 * 136);
            af[mt][2] = *(const uint32_t*)(ap + 8);
            af[mt][3] = *(const uint32_t*)(ap + 8 * 136 + 8);
        }
        #pragma unroll
        for (int nt = 0; nt < 4; nt++){
            const __half* bp = sB + (n0w + nt * 8 + gp) * 136 + k0 + 2 * tig;
            uint32_t b0 = *(const uint32_t*)bp;
            uint32_t b1 = *(const uint32_t*)(bp + 8);
            #pragma unroll
            for (int mt = 0; mt < 4; mt++)
                mma16816(acc[mt][nt][0], acc[mt][nt][1], acc[mt][nt][2], acc[mt][nt][3],
                         af[mt][0], af[mt][1], af[mt][2], af[mt][3], b0, b1);
        }
    }

    __syncthreads();
    __half* stg = sm;
    #pragma unroll
    for (int mt = 0; mt < 4; mt++){
        int ra = m0w + mt * 16 + gp;
        #pragma unroll
        for (int nt = 0; nt < 4; nt++){
            int nl = n0w + nt * 8 + 2 * tig;
            __half2 v0 = __floats2half2_rn(acc[mt][nt][0] + bias[nt].x, acc[mt][nt][1] + bias[nt].y);
            __half2 v1 = __floats2half2_rn(acc[mt][nt][2] + bias[nt].x, acc[mt][nt][3] + bias[nt].y);
            *(__half2*)(stg + ra * 136 + nl) = v0;
            *(__half2*)(stg + (ra + 8) * 136 + nl) = v1;
        }
    }
    __syncthreads();
    #pragma unroll
    for (int i = 0; i < 8; i++){
        int idx = tid + i * 256;
        int row = idx >> 4, col8 = (idx & 15) * 8;
        *(int4*)(g_xw2h + (size_t)(r0 + row) * 256 + n0c + col8) = *(const int4*)(stg + row * 136 + col8);
    }
}

// =====================================================================
// REC1 (tensor core v3): gate-pair layout -> shuffle-free epilogue,
// xw double-buffer prefetch. 128 CTAs x 8 rows, 8 warps.
// =====================================================================
__global__ void __launch_bounds__(256, 1) rec1_kernel()
{
    extern __shared__ __half smr[];
    __half* sB = smr;                  // [512][136]
    __half* sH = smr + 512 * 136;      // [2][8][136]
    const int tid  = threadIdx.x;
    const int w    = tid >> 5;
    const int lane = tid & 31;
    const int gp   = lane >> 2;
    const int tig  = lane & 3;
    const int b0   = blockIdx.x * 8;

    for (int idx = tid; idx < 8192; idx += 256){
        int nn = idx >> 4, c8 = (idx & 15) * 8;
        *(int4*)(sB + nn * 136 + c8) = *(const int4*)(g_w1hh + nn * 128 + c8);
    }
    for (int i = tid; i < 1088; i += 256) ((uint32_t*)sH)[i] = 0u;
    __syncthreads();

    uint32_t bb[4];
    {
        int rowo = (lane & 7) + ((lane & 16) ? 8 : 0);
        int kcol = ((lane >> 3) & 1) * 8;
        uint32_t base = smem_u32(sB);
        #pragma unroll
        for (int ntp = 0; ntp < 4; ntp++)
            bb[ntp] = base + (uint32_t)(((w * 64 + ntp * 16 + rowo) * 136 + kcol) * 2);
    }

    float cst[4] = {0.f, 0.f, 0.f, 0.f};
    const uint32_t zero = 0u;
    const int cA = w * 64 + 2 * tig;
    const int ubase = w * 16 + tig;    // unit for nt: ubase + nt*4

    // preload xw for t=0
    uint32_t xcur[8], xnxt[8];
    {
        const __half* xb = g_xw1h + ((size_t)b0 + gp) * 512 + cA;
        #pragma unroll
        for (int nt = 0; nt < 8; nt++) xcur[nt] = *(const uint32_t*)(xb + nt * 8);
    }

    for (int t = 0; t < 512; t++){
        const __half* hr = sH + (1 - (t & 1)) * 8 * 136;
        __half*       hw = sH + (t & 1) * 8 * 136;

        // prefetch xw for t+1 (consumed next step -> full-step latency cover)
        {
            int tn = (t < 511) ? t + 1 : t;
            const __half* xb = g_xw1h + ((size_t)tn * 1024 + b0 + gp) * 512 + cA;
            #pragma unroll
            for (int nt = 0; nt < 8; nt++) xnxt[nt] = *(const uint32_t*)(xb + nt * 8);
        }

        float acc[8][4];
        #pragma unroll
        for (int nt = 0; nt < 8; nt++){
            acc[nt][0]=0.f; acc[nt][1]=0.f; acc[nt][2]=0.f; acc[nt][3]=0.f;
        }

        #pragma unroll
        for (int kt = 0; kt < 8; kt++){
            const int k0 = kt * 16;
            const __half* ap = hr + gp * 136 + k0 + 2 * tig;
            uint32_t a0 = *(const uint32_t*)ap;
            uint32_t a2 = *(const uint32_t*)(ap + 8);
            #pragma unroll
            for (int ntp = 0; ntp < 4; ntp++){
                uint32_t r0, r1, r2, r3;
                ldsm_x4(r0, r1, r2, r3, bb[ntp] + (uint32_t)(k0 * 2));
                mma16816(acc[2*ntp][0],   acc[2*ntp][1],   acc[2*ntp][2],   acc[2*ntp][3],
                         a0, zero, a2, zero, r0, r1);
                mma16816(acc[2*ntp+1][0], acc[2*ntp+1][1], acc[2*ntp+1][2], acc[2*ntp+1][3],
                         a0, zero, a2, zero, r2, r3);
            }
        }

        // shuffle-free epilogue: nt has (i,f) of unit ubase+nt*4; nt+4 has (g,o)
        #pragma unroll
        for (int nt = 0; nt < 4; nt++){
            float2 xif = __half22float2(*(const __half2*)&xcur[nt]);
            float2 xgo = __half22float2(*(const __half2*)&xcur[nt + 4]);
            float gi = acc[nt][0]     + xif.x;
            float gf = acc[nt][1]     + xif.y;
            float gg = acc[nt + 4][0] + xgo.x;
            float go = acc[nt + 4][1] + xgo.y;
            float c = siga(gf) * cst[nt] + siga(gi) * tanha(gg);
            cst[nt] = c;
            float h = siga(go) * tanha(c);
            hw[gp * 136 + (ubase + nt * 4)] = __float2half(h);
        }
        #pragma unroll
        for (int nt = 0; nt < 8; nt++) xcur[nt] = xnxt[nt];
        __syncthreads();

        // coalesced copy h_t (8 x 128) -> g_hs1
        if (tid < 128){
            int row = tid >> 4, c8 = (tid & 15) * 8;
            *(int4*)(g_hs1 + ((size_t)t * 1024 + b0 + row) * 128 + c8) =
                *(const int4*)(hw + row * 136 + c8);
        }
    }
}

// =====================================================================
// REC2 (tensor core v3) + fused FC head. 128 CTAs x 8 rows, 8 warps.
// =====================================================================
__global__ void __launch_bounds__(256, 1) rec2_kernel(
    const float* __restrict__ fc1w, const float* __restrict__ fc1b,
    const float* __restrict__ fc2w, const float* __restrict__ fc2b,
    float* __restrict__ out)
{
    __shared__ __half sB[256 * 72];
    __shared__ __half sH[2 * 8 * 72];
    const int tid  = threadIdx.x;
    const int w    = tid >> 5;
    const int lane = tid & 31;
    const int gp   = lane >> 2;
    const int tig  = lane & 3;
    const int b0   = blockIdx.x * 8;

    for (int idx = tid; idx < 2048; idx += 256){
        int nn = idx >> 3, c8 = (idx & 7) * 8;
        *(int4*)(sB + nn * 72 + c8) = *(const int4*)(g_w2hh + nn * 64 + c8);
    }
    for (int i = tid; i < 576; i += 256) ((uint32_t*)sH)[i] = 0u;
    __syncthreads();

    uint32_t bb[2];
    {
        int rowo = (lane & 7) + ((lane & 16) ? 8 : 0);
        int kcol = ((lane >> 3) & 1) * 8;
        uint32_t base = smem_u32(sB);
        #pragma unroll
        for (int ntp = 0; ntp < 2; ntp++)
            bb[ntp] = base + (uint32_t)(((w * 32 + ntp * 16 + rowo) * 72 + kcol) * 2);
    }

    float cst[2] = {0.f, 0.f};
    const uint32_t zero = 0u;
    const int cA = w * 32 + 2 * tig;
    const int ubase = w * 8 + tig;     // unit for nt: ubase + nt*4

    uint32_t xcur[4], xnxt[4];
    {
        const __half* xb = g_xw2h + ((size_t)b0 + gp) * 256 + cA;
        #pragma unroll
        for (int nt = 0; nt < 4; nt++) xcur[nt] = *(const uint32_t*)(xb + nt * 8);
    }

    for (int t = 0; t < 512; t++){
        const __half* hr = sH + (1 - (t & 1)) * 8 * 72;
        __half*       hw = sH + (t & 1) * 8 * 72;

        {
            int tn = (t < 511) ? t + 1 : t;
            const __half* xb = g_xw2h + ((size_t)tn * 1024 + b0 + gp) * 256 + cA;
            #pragma unroll
            for (int nt = 0; nt < 4; nt++) xnxt[nt] = *(const uint32_t*)(xb + nt * 8);
        }

        float acc[4][4];
        #pragma unroll
        for (int nt = 0; nt < 4; nt++){
            acc[nt][0]=0.f; acc[nt][1]=0.f; acc[nt][2]=0.f; acc[nt][3]=0.f;
        }

        #pragma unroll
        for (int kt = 0; kt < 4; kt++){
            const int k0 = kt * 16;
            const __half* ap = hr + gp * 72 + k0 + 2 * tig;
            uint32_t a0 = *(const uint32_t*)ap;
            uint32_t a2 = *(const uint32_t*)(ap + 8);
            #pragma unroll
            for (int ntp = 0; ntp < 2; ntp++){
                uint32_t r0, r1, r2, r3;
                ldsm_x4(r0, r1, r2, r3, bb[ntp] + (uint32_t)(k0 * 2));
                mma16816(acc[2*ntp][0],   acc[2*ntp][1],   acc[2*ntp][2],   acc[2*ntp][3],
                         a0, zero, a2, zero, r0, r1);
                mma16816(acc[2*ntp+1][0], acc[2*ntp+1][1], acc[2*ntp+1][2], acc[2*ntp+1][3],
                         a0, zero, a2, zero, r2, r3);
            }
        }

        // shuffle-free epilogue: nt in {0,1} = (i,f) of unit ubase+nt*4; nt+2 = (g,o)
        #pragma unroll
        for (int nt = 0; nt < 2; nt++){
            float2 xif = __half22float2(*(const __half2*)&xcur[nt]);
            float2 xgo = __half22float2(*(const __half2*)&xcur[nt + 2]);
            float gi = acc[nt][0]     + xif.x;
            float gf = acc[nt][1]     + xif.y;
            float gg = acc[nt + 2][0] + xgo.x;
            float go = acc[nt + 2][1] + xgo.y;
            float c = siga(gf) * cst[nt] + siga(gi) * tanha(gg);
            cst[nt] = c;
            float h = siga(go) * tanha(c);
            hw[gp * 72 + (ubase + nt * 4)] = __float2half(h);
        }
        #pragma unroll
        for (int nt = 0; nt < 4; nt++) xcur[nt] = xnxt[nt];
        __syncthreads();
    }

    // ---- fused FC head: final h2 in buf 1 ----
    const __half* hf = sH + 8 * 72;
    const int m = w, r = lane;
    float s = (r < 32) ? fc1b[r] : 0.f;
    #pragma unroll 8
    for (int k = 0; k < 64; k++)
        s += __half2float(hf[m * 72 + k]) * fc1w[r * 64 + k];
    float z = fmaxf(s, 0.f) * fc2w[r];
    #pragma unroll
    for (int off = 16; off > 0; off >>= 1)
        z += __shfl_xor_sync(0xffffffffu, z, off);
    if (r == 0) out[b0 + m] = sigf(z + fc2b[0]);
}

// =====================================================================
extern "C" void kernel_launch(void* const* d_in, const int* in_sizes, int n_in,
                              void* d_out, int out_size)
{
    const float* X     = (const float*)d_in[0];
    const float* W1_ih = (const float*)d_in[1];
    const float* W1_hh = (const float*)d_in[2];
    const float* b1_ih = (const float*)d_in[3];
    const float* b1_hh = (const float*)d_in[4];
    const float* W2_ih = (const float*)d_in[5];
    const float* W2_hh = (const float*)d_in[6];
    const float* b2_ih = (const float*)d_in[7];
    const float* b2_hh = (const float*)d_in[8];
    const float* fc1w  = (const float*)d_in[9];
    const float* fc1b  = (const float*)d_in[10];
    const float* fc2w  = (const float*)d_in[11];
    const float* fc2b  = (const float*)d_in[12];
    float* out = (float*)d_out;

    const int g1_smem = 2 * 128 * 120 * 2;             // 61440 B
    const int g2_smem = 2 * 128 * 136 * 2;             // 69632 B
    const int r1_smem = (512 * 136 + 2 * 8 * 136) * 2; // 143616 B

    cudaFuncSetAttribute(gemm1_tc,    cudaFuncAttributeMaxDynamicSharedMemorySize, g1_smem);
    cudaFuncSetAttribute(gemm2_tc,    cudaFuncAttributeMaxDynamicSharedMemorySize, g2_smem);
    cudaFuncSetAttribute(rec1_kernel, cudaFuncAttributeMaxDynamicSharedMemorySize, r1_smem);

    prep_kernel<<<128, 256>>>(W1_ih, W1_hh, b1_ih, b1_hh, W2_ih, W2_hh, b2_ih, b2_hh);
    gemm1_tc<<<dim3(4, 4096), 256, g1_smem>>>(X);
    rec1_kernel<<<128, 256, r1_smem>>>();
    gemm2_tc<<<dim3(2, 4096), 256, g2_smem>>>();
    rec2_kernel<<<128, 256>>>(fc1w, fc1b, fc2w, fc2b, out);
}